// round 14
// baseline (speedup 1.0000x reference)
#include <cuda_runtime.h>
#include <cuda_bf16.h>
#include <math.h>
#include <stdint.h>

// Problem constants
#define BB 2
#define SS 1024
#define HH 16
#define DD 64
#define DM 1024
#define NRS 129        // slim rel width: indices 128..256 of the full table

// Scratch (device globals)
__device__ float g_Q[BB*SS*DM];
__device__ float g_K[BB*SS*DM];
__device__ float g_V[BB*SS*DM];
__device__ float g_qbar[BB*HH*SS*DD];
__device__ float g_Rbar[BB*HH*SS*NRS];
__device__ float g_S[BB*HH*SS*SS];
__device__ float g_Ap[BB*HH*SS*NRS];
__device__ float g_ctx[BB*SS*DM];
__device__ float g_ropeT[2048*64];

__device__ __forceinline__ unsigned f2tf32(float v) {
    unsigned u;
    asm("cvt.rna.tf32.f32 %0, %1;" : "=r"(u) : "f"(v));
    return u;
}

__device__ __forceinline__ void mma_tf32(float c[4],
                                         unsigned a0, unsigned a1, unsigned a2, unsigned a3,
                                         unsigned b0, unsigned b1) {
    asm volatile("mma.sync.aligned.m16n8k8.row.col.f32.tf32.tf32.f32 "
                 "{%0,%1,%2,%3}, {%4,%5,%6,%7}, {%8,%9}, {%0,%1,%2,%3};"
                 : "+f"(c[0]), "+f"(c[1]), "+f"(c[2]), "+f"(c[3])
                 : "r"(a0), "r"(a1), "r"(a2), "r"(a3), "r"(b0), "r"(b1));
}

// ===========================================================================
// 128x128 tf32 GEMM core (warp tile 64x32, K-step 16) — used by qk128 only
// ===========================================================================
#define T_AW 2048
#define T_BW 2048
#define T_BUF (T_AW + T_BW)
#define T_LDST 132
#define T_SMEM_BYTES (64 * T_LDST * 4)

#define GEMM128_BODY(TRANSB_, KTOT, Aptr, Bptr, lda_, ldb_)                          \
    float acc[4][4][4];                                                              \
    _Pragma("unroll")                                                                \
    for (int i = 0; i < 4; i++)                                                      \
        _Pragma("unroll")                                                            \
        for (int j = 0; j < 4; j++)                                                  \
            _Pragma("unroll")                                                        \
            for (int e = 0; e < 4; e++) acc[i][j][e] = 0.f;                          \
    float aPf[8], bPf[8];                                                            \
    int ra = tid >> 4, ka = tid & 15;                                                \
    auto fetchA = [&](int kt) {                                                      \
        _Pragma("unroll")                                                            \
        for (int u = 0; u < 8; u++)                                                  \
            aPf[u] = Aptr[(long)(m0 + ra + u * 16) * lda_ + kt + ka];                \
    };                                                                               \
    auto fetchB = [&](int kt) {                                                      \
        _Pragma("unroll")                                                            \
        for (int u = 0; u < 8; u++) {                                                \
            int idx = tid + u * 256;                                                 \
            if (TRANSB_) {                                                           \
                int n = idx >> 4, kk = idx & 15;                                     \
                bPf[u] = Bptr[(long)(n0 + n) * ldb_ + kt + kk];                      \
            } else {                                                                 \
                int kk = idx >> 7, n = idx & 127;                                    \
                bPf[u] = Bptr[(long)(kt + kk) * ldb_ + n0 + n];                      \
            }                                                                        \
        }                                                                            \
    };                                                                               \
    auto storeBuf = [&](int buf) {                                                   \
        unsigned* Af = base + buf * T_BUF;                                           \
        unsigned* Bf = Af + T_AW;                                                    \
        _Pragma("unroll")                                                            \
        for (int u = 0; u < 8; u++) {                                                \
            int r = ra + u * 16, kk = ka;                                            \
            int blk = r >> 4, rr = r & 15;                                           \
            int ks8 = kk >> 3, kt7 = kk & 7;                                         \
            int dl = ((rr & 7) << 2) | (kt7 & 3);                                    \
            int w  = ((rr >> 3) & 1) | ((kt7 >> 2) << 1);                            \
            Af[(((blk << 1) | ks8) << 7) + (dl << 2) + w] = f2tf32(aPf[u]);          \
        }                                                                            \
        _Pragma("unroll")                                                            \
        for (int u = 0; u < 8; u++) {                                                \
            int idx = tid + u * 256;                                                 \
            int n, kk;                                                               \
            if (TRANSB_) { n = idx >> 4; kk = idx & 15; }                            \
            else         { kk = idx >> 7; n = idx & 127; }                           \
            int nb8 = n >> 3, gg = n & 7;                                            \
            int ks8 = kk >> 3, kt7 = kk & 7;                                         \
            int dl = (gg << 2) | (kt7 & 3);                                          \
            int w  = (kt7 >> 2) & 1;                                                 \
            Bf[(((nb8 << 1) | ks8) << 6) + (dl << 1) + w] = f2tf32(bPf[u]);          \
        }                                                                            \
    };                                                                               \
    fetchA(0); fetchB(0);                                                            \
    storeBuf(0);                                                                     \
    __syncthreads();                                                                 \
    int cur = 0;                                                                     \
    for (int kt = 0; kt < (KTOT); kt += 16) {                                        \
        bool hn = (kt + 16) < (KTOT);                                                \
        if (hn) { fetchA(kt + 16); fetchB(kt + 16); }                                \
        unsigned* Af = base + cur * T_BUF;                                           \
        unsigned* Bf = Af + T_AW;                                                    \
        _Pragma("unroll")                                                            \
        for (int ks8 = 0; ks8 < 2; ks8++) {                                          \
            uint4 av[4];                                                             \
            _Pragma("unroll")                                                        \
            for (int i = 0; i < 4; i++) {                                            \
                int blk = wm * 4 + i;                                                \
                av[i] = *(const uint4*)&Af[(((blk << 1) | ks8) << 7) + (lane << 2)]; \
            }                                                                        \
            _Pragma("unroll")                                                        \
            for (int j = 0; j < 4; j++) {                                            \
                int nb8 = wn * 4 + j;                                                \
                uint2 bv = *(const uint2*)&Bf[(((nb8 << 1) | ks8) << 6) + (lane << 1)]; \
                _Pragma("unroll")                                                    \
                for (int i = 0; i < 4; i++)                                          \
                    mma_tf32(acc[i][j], av[i].x, av[i].y, av[i].z, av[i].w, bv.x, bv.y); \
            }                                                                        \
        }                                                                            \
        if (hn) storeBuf(cur ^ 1);                                                   \
        __syncthreads();                                                             \
        cur ^= 1;                                                                    \
    }

#define STAGE_STORE(step_)                                                           \
    if (wm == (step_)) {                                                             \
        _Pragma("unroll")                                                            \
        for (int i = 0; i < 4; i++)                                                  \
            _Pragma("unroll")                                                        \
            for (int j = 0; j < 4; j++) {                                            \
                int r0 = i * 16 + g;                                                 \
                int c0 = wn * 32 + j * 8 + 2 * t;                                    \
                stage[ r0      * T_LDST + c0    ] = acc[i][j][0];                    \
                stage[ r0      * T_LDST + c0 + 1] = acc[i][j][1];                    \
                stage[(r0 + 8) * T_LDST + c0    ] = acc[i][j][2];                    \
                stage[(r0 + 8) * T_LDST + c0 + 1] = acc[i][j][3];                    \
            }                                                                        \
    }

// ---------------------------------------------------------------------------
// QK^T kernel, causal tile skip (T128 tile)
// ---------------------------------------------------------------------------
__global__ void __launch_bounds__(256, 2)
qk128_kernel(const float* __restrict__ Qm, const float* __restrict__ Km,
             float* __restrict__ S)
{
    extern __shared__ __align__(16) unsigned char dynsm[];
    unsigned* base = (unsigned*)dynsm;
    float* stage = (float*)dynsm;

    int m0 = blockIdx.y * 128, n0 = blockIdx.x * 128;
    if (n0 > m0) return;

    int z = blockIdx.z;
    int b = z >> 4, h = z & 15;
    const float* A = Qm + (long)b * SS * DM + h * 64;
    const float* Bp = Km + (long)b * SS * DM + h * 64;
    float* C = S + (long)z * SS * SS;

    int tid = threadIdx.x;
    int wid = tid >> 5, lane = tid & 31;
    int wm = wid >> 2, wn = wid & 3;
    int g = lane >> 2, t = lane & 3;

    GEMM128_BODY(true, 64, A, Bp, DM, DM)

    #pragma unroll
    for (int step = 0; step < 2; step++) {
        STAGE_STORE(step)
        __syncthreads();
        #pragma unroll
        for (int u = 0; u < 8; u++) {
            int idx = tid + u * 256;
            int r = idx >> 5, c4 = idx & 31;
            int c = c4 * 4;
            int gm = m0 + step * 64 + r;
            float4 v = *(const float4*)(stage + r * T_LDST + c);
            *(float4*)(C + (long)gm * SS + n0 + c) = v;
        }
        __syncthreads();
    }
}

// ---------------------------------------------------------------------------
// TN=64 machinery
// ---------------------------------------------------------------------------
#define G_AWORDS 4096
#define G_BWORDS 2048
#define G_BUF (G_AWORDS + G_BWORDS)
#define G_LDST 68
#define G_SMEM_BYTES (2 * G_BUF * 4)

#define G64_DECLS                                                                   \
    int tid = threadIdx.x;                                                          \
    int wid = tid >> 5, lane = tid & 31;                                            \
    int wm = wid >> 1;                                                              \
    int wn = wid & 1;                                                               \
    int g = lane >> 2, t = lane & 3;                                                \
    int ra = tid >> 5, ka = tid & 31;                                               \
    float acc[2][4][4];                                                             \
    _Pragma("unroll")                                                               \
    for (int i = 0; i < 2; i++)                                                     \
        _Pragma("unroll")                                                           \
        for (int j = 0; j < 4; j++)                                                 \
            _Pragma("unroll")                                                       \
            for (int e = 0; e < 4; e++) acc[i][j][e] = 0.f;                         \
    float aPf[16], bPf[8];

#define G64_STOREBUF(buf, TRANSB_)                                                  \
    {                                                                               \
        unsigned* Af = base + (buf) * G_BUF;                                        \
        unsigned* Bf = Af + G_AWORDS;                                               \
        _Pragma("unroll")                                                           \
        for (int u = 0; u < 16; u++) {                                              \
            int r = ra + u * 8, kk = ka;                                            \
            int blk = r >> 4, rr = r & 15;                                          \
            int ks8 = kk >> 3, kt7 = kk & 7;                                        \
            int dl = ((rr & 7) << 2) | (kt7 & 3);                                   \
            int w  = ((rr >> 3) & 1) | ((kt7 >> 2) << 1);                           \
            Af[(((blk << 2) + ks8) << 7) + (dl << 2) + w] = f2tf32(aPf[u]);         \
        }                                                                           \
        _Pragma("unroll")                                                           \
        for (int u = 0; u < 8; u++) {                                               \
            int idx = tid + u * 256;                                                \
            int n, kk;                                                              \
            if (TRANSB_) { n = idx >> 5; kk = idx & 31; }                           \
            else         { kk = idx >> 6; n = idx & 63; }                           \
            int nb8 = n >> 3, gg = n & 7;                                           \
            int ks8 = kk >> 3, kt7 = kk & 7;                                        \
            int dl = (gg << 2) | (kt7 & 3);                                         \
            int w  = (kt7 >> 2) & 1;                                                \
            Bf[(((nb8 << 2) + ks8) << 6) + (dl << 1) + w] = f2tf32(bPf[u]);         \
        }                                                                           \
    }

#define G64_MMA(bufc)                                                               \
    {                                                                               \
        unsigned* Af = base + (bufc) * G_BUF;                                       \
        unsigned* Bf = Af + G_AWORDS;                                               \
        _Pragma("unroll")                                                           \
        for (int ks8 = 0; ks8 < 4; ks8++) {                                         \
            uint4 av[2];                                                            \
            _Pragma("unroll")                                                       \
            for (int i = 0; i < 2; i++) {                                           \
                int blk = wm * 2 + i;                                               \
                av[i] = *(const uint4*)&Af[(((blk << 2) + ks8) << 7) + (lane << 2)];\
            }                                                                       \
            _Pragma("unroll")                                                       \
            for (int j = 0; j < 4; j++) {                                           \
                int nb8 = wn * 4 + j;                                               \
                uint2 bv = *(const uint2*)&Bf[(((nb8 << 2) + ks8) << 6) + (lane << 1)]; \
                _Pragma("unroll")                                                   \
                for (int i = 0; i < 2; i++)                                         \
                    mma_tf32(acc[i][j], av[i].x, av[i].y, av[i].z, av[i].w, bv.x, bv.y); \
            }                                                                       \
        }                                                                           \
    }

#define G64_EPILOGUE_STAGE()                                                        \
    _Pragma("unroll")                                                               \
    for (int step = 0; step < 2; step++) {                                          \
        if ((wm >> 1) == step) {                                                    \
            int rbase = (wm & 1) * 32;                                              \
            _Pragma("unroll")                                                       \
            for (int i = 0; i < 2; i++)                                             \
                _Pragma("unroll")                                                   \
                for (int j = 0; j < 4; j++) {                                       \
                    int r0 = rbase + i * 16 + g;                                    \
                    int c0 = wn * 32 + j * 8 + 2 * t;                               \
                    stage[ r0      * G_LDST + c0    ] = acc[i][j][0];               \
                    stage[ r0      * G_LDST + c0 + 1] = acc[i][j][1];               \
                    stage[(r0 + 8) * G_LDST + c0    ] = acc[i][j][2];               \
                    stage[(r0 + 8) * G_LDST + c0 + 1] = acc[i][j][3];               \
                }                                                                   \
        }                                                                           \
        __syncthreads();                                                            \
        G64_WRITE(step)                                                             \
        __syncthreads();                                                            \
    }

// ---------------------------------------------------------------------------
// QKV projection (G64 tile, grid 16x16x3), fused bias + optional RoPE
// ---------------------------------------------------------------------------
struct Proj3 {
    const float* A[3];
    const float* W[3];
    float*       C[3];
    const float* bias[3];
    const int*   pos[3];
};

__global__ void __launch_bounds__(256, 2)
proj64_kernel(Proj3 p, const float* __restrict__ ropeTab)
{
    extern __shared__ __align__(16) unsigned char dynsm[];
    unsigned* base = (unsigned*)dynsm;
    float* stage = (float*)dynsm;

    int z = blockIdx.z;
    const float* A = p.A[z];
    const float* W = p.W[z];
    float* C = p.C[z];
    const float* bias = p.bias[z];
    const int* posIds = p.pos[z];

    int m0 = blockIdx.y * 128, n0 = blockIdx.x * 64;

    G64_DECLS

    auto fetchA = [&](int kt) {
        #pragma unroll
        for (int u = 0; u < 16; u++)
            aPf[u] = A[(long)(m0 + ra + u * 8) * DM + kt + ka];
    };
    auto fetchB = [&](int kt) {
        #pragma unroll
        for (int u = 0; u < 8; u++) {
            int idx = tid + u * 256;
            int n = idx >> 5, kk = idx & 31;
            bPf[u] = W[(long)(n0 + n) * DM + kt + kk];
        }
    };

    fetchA(0); fetchB(0);
    G64_STOREBUF(0, true)
    __syncthreads();
    int cur = 0;
    for (int kt = 0; kt < DM; kt += 32) {
        bool hn = (kt + 32) < DM;
        if (hn) { fetchA(kt + 32); fetchB(kt + 32); }
        G64_MMA(cur)
        if (hn) G64_STOREBUF(cur ^ 1, true)
        __syncthreads();
        cur ^= 1;
    }

#define G64_WRITE(step_)                                                            \
        _Pragma("unroll")                                                           \
        for (int u = 0; u < 4; u++) {                                               \
            int idx = tid + u * 256;                                                \
            int r = idx >> 4, c4 = idx & 15;                                        \
            int c = c4 * 4;                                                         \
            int gm = m0 + (step_) * 64 + r;                                         \
            float4 v = *(const float4*)(stage + r * G_LDST + c);                    \
            float4 bv = *(const float4*)(bias + n0 + c);                            \
            v.x += bv.x; v.y += bv.y; v.z += bv.z; v.w += bv.w;                     \
            if (posIds) {                                                           \
                float4 w = *(const float4*)(stage + r * G_LDST + (c ^ 32));         \
                float4 bw = *(const float4*)(bias + n0 + (c ^ 32));                 \
                w.x += bw.x; w.y += bw.y; w.z += bw.z; w.w += bw.w;                 \
                int bb = gm >> 10, s = gm & 1023;                                   \
                int pos = posIds[(bb << 10) + s];                                   \
                int i0 = c & 31;                                                    \
                float4 co = *(const float4*)(ropeTab + pos * 64 + i0);              \
                float4 si = *(const float4*)(ropeTab + pos * 64 + 32 + i0);         \
                if ((c & 32) == 0) {                                                \
                    v.x = v.x * co.x - w.x * si.x;                                  \
                    v.y = v.y * co.y - w.y * si.y;                                  \
                    v.z = v.z * co.z - w.z * si.z;                                  \
                    v.w = v.w * co.w - w.w * si.w;                                  \
                } else {                                                            \
                    v.x = v.x * co.x + w.x * si.x;                                  \
                    v.y = v.y * co.y + w.y * si.y;                                  \
                    v.z = v.z * co.z + w.z * si.z;                                  \
                    v.w = v.w * co.w + w.w * si.w;                                  \
                }                                                                   \
            }                                                                       \
            *(float4*)(C + (long)gm * DM + n0 + c) = v;                             \
        }
    G64_EPILOGUE_STAGE()
#undef G64_WRITE
}

// ---------------------------------------------------------------------------
// Rbar kernel: C[32768, 0..127] = A[32768,64] @ B[128,64]^T (unguarded)
// ---------------------------------------------------------------------------
__global__ void __launch_bounds__(256, 2)
rbar_kernel(const float* __restrict__ A, const float* __restrict__ Bm,
            float* __restrict__ C)
{
    extern __shared__ __align__(16) unsigned char dynsm[];
    unsigned* base = (unsigned*)dynsm;
    float* stage = (float*)dynsm;

    const int K = 64;
    int m0 = blockIdx.y * 128, n0 = blockIdx.x * 64;

    G64_DECLS

    auto fetchA = [&](int kt) {
        #pragma unroll
        for (int u = 0; u < 16; u++) {
            int r = ra + u * 8;
            aPf[u] = A[(long)(m0 + r) * 64 + kt + ka];
        }
    };
    auto fetchB = [&](int kt) {
        #pragma unroll
        for (int u = 0; u < 8; u++) {
            int idx = tid + u * 256;
            int n = idx >> 5, kk = idx & 31;
            bPf[u] = Bm[(long)(n0 + n) * 64 + kt + kk];
        }
    };

    fetchA(0); fetchB(0);
    G64_STOREBUF(0, true)
    __syncthreads();
    int cur = 0;
    for (int kt = 0; kt < K; kt += 32) {
        bool hn = (kt + 32) < K;
        if (hn) { fetchA(kt + 32); fetchB(kt + 32); }
        G64_MMA(cur)
        if (hn) G64_STOREBUF(cur ^ 1, true)
        __syncthreads();
        cur ^= 1;
    }

#define G64_WRITE(step_)                                                            \
        _Pragma("unroll")                                                           \
        for (int u = 0; u < 16; u++) {                                              \
            int idx = tid + u * 256;                                                \
            int r = idx >> 6, c = idx & 63;                                         \
            int gm = m0 + (step_) * 64 + r, gn = n0 + c;                            \
            C[(long)gm * NRS + gn] = stage[r * G_LDST + c];                         \
        }
    G64_EPILOGUE_STAGE()
#undef G64_WRITE
}

// ---------------------------------------------------------------------------
// rcol: Rbar column 128 = qbar . relk[256] (exact fp32 dot per row)
// 256 threads/block, 8 threads per row, 32 rows/block, grid 1024
// ---------------------------------------------------------------------------
__global__ void rcol_kernel(const float* __restrict__ qbar,
                            const float* __restrict__ relk256,
                            float* __restrict__ Rbar)
{
    __shared__ float rk[64];
    int tid = threadIdx.x;
    if (tid < 64) rk[tid] = relk256[tid];
    __syncthreads();

    int row = blockIdx.x * 32 + (tid >> 3);
    int part = tid & 7;
    const float* qr = qbar + (long)row * 64 + part * 8;
    float4 a0 = *(const float4*)qr;
    float4 a1 = *(const float4*)(qr + 4);
    const float* rp = rk + part * 8;
    float s = a0.x * rp[0] + a0.y * rp[1] + a0.z * rp[2] + a0.w * rp[3]
            + a1.x * rp[4] + a1.y * rp[5] + a1.z * rp[6] + a1.w * rp[7];
    s += __shfl_down_sync(0xffffffffu, s, 4);
    s += __shfl_down_sync(0xffffffffu, s, 2);
    s += __shfl_down_sync(0xffffffffu, s, 1);
    if (part == 0) Rbar[(long)row * NRS + 128] = s;
}

// ---------------------------------------------------------------------------
// Fused AV kernel: ctx = attn @ V + Ap[:,0:128] @ relv'[0:128] + rank-1(j=128)
// ---------------------------------------------------------------------------
__global__ void __launch_bounds__(256, 2)
av_fused_kernel(const float* __restrict__ Sc, const float* __restrict__ Vm,
                const float* __restrict__ Ap, const float* __restrict__ relv2,
                float* __restrict__ ctx)
{
    extern __shared__ __align__(16) unsigned char dynsm[];
    unsigned* base = (unsigned*)dynsm;
    float* stage = (float*)dynsm;

    int m0 = blockIdx.y * 128;
    int z = blockIdx.z;
    int b = z >> 4, h = z & 15;
    int Keff = m0 + 128;

    const float* A  = Sc + (long)z * SS * SS;
    const float* Bv = Vm + (long)b * SS * DM + h * 64;
    const float* A2 = Ap + (long)z * SS * NRS;
    float* C = ctx + (long)b * SS * DM + h * 64;

    G64_DECLS

    auto fetchA1 = [&](int kt) {
        #pragma unroll
        for (int u = 0; u < 16; u++)
            aPf[u] = A[(long)(m0 + ra + u * 8) * SS + kt + ka];
    };
    auto fetchB1 = [&](int kt) {
        #pragma unroll
        for (int u = 0; u < 8; u++) {
            int idx = tid + u * 256;
            int kk = idx >> 6, n = idx & 63;
            bPf[u] = Bv[(long)(kt + kk) * DM + n];
        }
    };
    auto fetchA2 = [&](int kt) {
        #pragma unroll
        for (int u = 0; u < 16; u++)
            aPf[u] = A2[(long)(m0 + ra + u * 8) * NRS + kt + ka];
    };
    auto fetchB2 = [&](int kt) {
        #pragma unroll
        for (int u = 0; u < 8; u++) {
            int idx = tid + u * 256;
            int kk = idx >> 6, n = idx & 63;
            bPf[u] = relv2[(long)(kt + kk) * 64 + n];
        }
    };

    const int K2 = 128;
    fetchA1(0); fetchB1(0);
    G64_STOREBUF(0, false)
    __syncthreads();
    int cur = 0;
    for (int kt = 0; kt < Keff; kt += 32) {
        bool hn = (kt + 32) < Keff;
        if (hn)      { fetchA1(kt + 32); fetchB1(kt + 32); }
        else         { fetchA2(0);       fetchB2(0);       }
        G64_MMA(cur)
        G64_STOREBUF(cur ^ 1, false)
        __syncthreads();
        cur ^= 1;
    }
    for (int kt = 0; kt < K2; kt += 32) {
        bool hn = (kt + 32) < K2;
        if (hn) { fetchA2(kt + 32); fetchB2(kt + 32); }
        G64_MMA(cur)
        if (hn) G64_STOREBUF(cur ^ 1, false)
        __syncthreads();
        cur ^= 1;
    }

#define G64_WRITE(step_)                                                            \
        _Pragma("unroll")                                                           \
        for (int u = 0; u < 4; u++) {                                               \
            int idx = tid + u * 256;                                                \
            int r = idx >> 4, c4 = idx & 15;                                        \
            int c = c4 * 4;                                                         \
            int gm = m0 + (step_) * 64 + r;                                         \
            float4 v = *(const float4*)(stage + r * G_LDST + c);                    \
            float apv = A2[(long)gm * NRS + 128];                                   \
            float4 rv = *(const float4*)(relv2 + 128 * 64 + c);                     \
            v.x += apv * rv.x; v.y += apv * rv.y;                                   \
            v.z += apv * rv.z; v.w += apv * rv.w;                                   \
            *(float4*)(C + (long)gm * DM + c) = v;                                  \
        }
    G64_EPILOGUE_STAGE()
#undef G64_WRITE
}

// ---------------------------------------------------------------------------
// Wo kernel (TN=64 tiles)
// ---------------------------------------------------------------------------
__global__ void __launch_bounds__(256, 2)
wo64_kernel(const float* __restrict__ A, const float* __restrict__ W,
            float* __restrict__ C, const float* __restrict__ bias)
{
    extern __shared__ __align__(16) unsigned char dynsm[];
    unsigned* base = (unsigned*)dynsm;
    float* stage = (float*)dynsm;

    int m0 = blockIdx.y * 128, n0 = blockIdx.x * 64;

    G64_DECLS

    auto fetchA = [&](int kt) {
        #pragma unroll
        for (int u = 0; u < 16; u++)
            aPf[u] = A[(long)(m0 + ra + u * 8) * DM + kt + ka];
    };
    auto fetchB = [&](int kt) {
        #pragma unroll
        for (int u = 0; u < 8; u++) {
            int idx = tid + u * 256;
            int n = idx >> 5, kk = idx & 31;
            bPf[u] = W[(long)(n0 + n) * DM + kt + kk];
        }
    };

    fetchA(0); fetchB(0);
    G64_STOREBUF(0, true)
    __syncthreads();
    int cur = 0;
    for (int kt = 0; kt < DM; kt += 32) {
        bool hn = (kt + 32) < DM;
        if (hn) { fetchA(kt + 32); fetchB(kt + 32); }
        G64_MMA(cur)
        if (hn) G64_STOREBUF(cur ^ 1, true)
        __syncthreads();
        cur ^= 1;
    }

#define G64_WRITE(step_)                                                            \
        _Pragma("unroll")                                                           \
        for (int u = 0; u < 4; u++) {                                               \
            int idx = tid + u * 256;                                                \
            int r = idx >> 4, c4 = idx & 15;                                        \
            int c = c4 * 4;                                                         \
            int gm = m0 + (step_) * 64 + r;                                         \
            float4 v = *(const float4*)(stage + r * G_LDST + c);                    \
            float4 bv = *(const float4*)(bias + n0 + c);                            \
            v.x += bv.x; v.y += bv.y; v.z += bv.z; v.w += bv.w;                     \
            *(float4*)(C + (long)gm * DM + n0 + c) = v;                             \
        }
    G64_EPILOGUE_STAGE()
#undef G64_WRITE
}

// ---------------------------------------------------------------------------
// RoPE table
// ---------------------------------------------------------------------------
__global__ void rope_table_kernel(float* __restrict__ T)
{
    int idx = blockIdx.x * blockDim.x + threadIdx.x;
    if (idx >= 2048 * 32) return;
    int i = idx & 31, pos = idx >> 5;
    double inv = exp(-(double)i / 32.0 * log(10000.0));
    double ds, dc;
    sincos((double)pos * inv, &ds, &dc);
    T[pos * 64 + i]      = (float)dc;
    T[pos * 64 + 32 + i] = (float)ds;
}

// ---------------------------------------------------------------------------
// qbar v2
// ---------------------------------------------------------------------------
__global__ void qbar_kernel(const float* __restrict__ Q, const float* __restrict__ wpre,
                            float* __restrict__ qbar)
{
    __shared__ float sw[256];
    if (threadIdx.x < 256) sw[threadIdx.x] = wpre[threadIdx.x];
    __syncthreads();

    int idx = blockIdx.x * blockDim.x + threadIdx.x;
    if (idx >= BB * SS * DD) return;
    int d = idx & 63;
    int s = (idx >> 6) & 1023;
    int b = idx >> 16;
    const float* qrow = Q + ((size_t)(b * SS + s)) * DM + d;
    float qv[16];
    #pragma unroll
    for (int n = 0; n < 16; n++) qv[n] = qrow[n * 64];
    #pragma unroll
    for (int m = 0; m < 16; m++) {
        float acc = 0.f;
        #pragma unroll
        for (int n = 0; n < 16; n++) acc += sw[n * 16 + m] * qv[n];
        qbar[(((size_t)(b * 16 + m)) * SS + s) * DD + d] = acc;
    }
}

// ---------------------------------------------------------------------------
// mix_softmax — round-11 version (fixed 1024 stride, causal I/O)
// ---------------------------------------------------------------------------
#define MIX_SMEM ((16*1024 + 16*NRS + 256 + 256 + 16 + 16) * 4)

__global__ void __launch_bounds__(512)
mix_softmax_kernel(float* __restrict__ S, const float* __restrict__ Rbar,
                   const float* __restrict__ wpre, const float* __restrict__ wpost,
                   float* __restrict__ Ap)
{
    extern __shared__ float shm[];
    float* sm     = shm;
    float* srb    = sm + 16 * 1024;
    float* swpre  = srb + 16 * NRS;
    float* swpost = swpre + 256;
    float* sinv   = swpost + 256;
    float* stail  = sinv + 16;

    int q = blockIdx.x, b = blockIdx.y;
    int tid = threadIdx.x;
    int wid = tid >> 5, lane = tid & 31;
    int KW4 = ((q >> 7) + 1) << 5;
    int KW  = KW4 << 2;

    if (tid < 256) { swpre[tid] = wpre[tid]; swpost[tid] = wpost[tid]; }
    {
        const long rowBase = ((long)(b * 16) * SS + q) * SS;
        for (int tt = tid; tt < 16 * 256; tt += 512) {
            int n = tt >> 8, k4 = tt & 255;
            if (k4 < KW4)
                ((float4*)sm)[n * 256 + k4] =
                    *(const float4*)(S + rowBase + (long)n * SS * SS + k4 * 4);
        }
    }
    for (int tt = tid; tt < 16 * NRS; tt += 512) {
        int m = tt / NRS, j = tt - m * NRS;
        srb[tt] = Rbar[((size_t)(b * 16 + m) * SS + q) * NRS + j];
    }
    __syncthreads();

    for (int k = tid; k <= q; k += 512) {
        float r[16];
        #pragma unroll
        for (int n = 0; n < 16; n++) r[n] = sm[n * 1024 + k];
        int d = q - k;
        int cl = d > 128 ? 128 : d;
        #pragma unroll
        for (int m = 0; m < 16; m++) {
            float accv = 0.f;
            #pragma unroll
            for (int n = 0; n < 16; n++) accv += swpre[n * 16 + m] * r[n];
            sm[m * 1024 + k] = (accv + srb[m * NRS + cl]) * 0.125f;
        }
    }
    __syncthreads();

    {
        int m = wid;
        float mx = -1e30f;
        for (int k = lane; k <= q; k += 32) mx = fmaxf(mx, sm[m * 1024 + k]);
        #pragma unroll
        for (int o = 16; o; o >>= 1) mx = fmaxf(mx, __shfl_xor_sync(0xffffffffu, mx, o));
        float sum = 0.f;
        for (int k = lane; k <= q; k += 32) {
            float p = __expf(sm[m * 1024 + k] - mx);
            sm[m * 1024 + k] = p;
            sum += p;
        }
        #pragma unroll
        for (int o = 16; o; o >>= 1) sum += __shfl_xor_sync(0xffffffffu, sum, o);
        for (int k = q + 1 + lane; k < KW; k += 32) sm[m * 1024 + k] = 0.f;
        if (lane == 0) sinv[m] = 1.f / sum;
    }
    __syncthreads();

    float inv[16];
    #pragma unroll
    for (int m = 0; m < 16; m++) inv[m] = sinv[m];
    for (int k = tid; k <= q; k += 512) {
        float p[16];
        #pragma unroll
        for (int m = 0; m < 16; m++) p[m] = sm[m * 1024 + k] * inv[m];
        #pragma unroll
        for (int n = 0; n < 16; n++) {
            float accv = 0.f;
            #pragma unroll
            for (int m = 0; m < 16; m++) accv += p[m] * swpost[m * 16 + n];
            sm[n * 1024 + k] = accv;
        }
    }
    __syncthreads();

    {
        const long rowBase = ((long)(b * 16) * SS + q) * SS;
        for (int tt = tid; tt < 16 * 256; tt += 512) {
            int n = tt >> 8, k4 = tt & 255;
            if (k4 < KW4)
                *(float4*)(S + rowBase + (long)n * SS * SS + k4 * 4) =
                    ((float4*)sm)[n * 256 + k4];
        }
    }
    {
        int m = wid;
        float ts = 0.f;
        for (int k = lane; k <= q - 128; k += 32) ts += sm[m * 1024 + k];
        #pragma unroll
        for (int o = 16; o; o >>= 1) ts += __shfl_xor_sync(0xffffffffu, ts, o);
        if (lane == 0) stail[m] = ts;
    }
    __syncthreads();

    for (int tt = tid; tt < 16 * NRS; tt += 512) {
        int n = tt / NRS, j = tt - n * NRS;
        float v = 0.f;
        if (j == 128) v = stail[n];
        else {
            int k = q - j;
            if (k >= 0) v = sm[n * 1024 + k];
        }
        Ap[((size_t)(b * 16 + n) * SS + q) * NRS + j] = v;
    }
}

// ---------------------------------------------------------------------------
// Launch sequence
// ---------------------------------------------------------------------------
extern "C" void kernel_launch(void* const* d_in, const int* in_sizes, int n_in,
                              void* d_out, int out_size)
{
    const float* query = (const float*)d_in[0];
    const float* key_  = (const float*)d_in[1];
    const float* value = (const float*)d_in[2];
    const int*   qpos  = (const int*)d_in[4];
    const int*   kpos  = (const int*)d_in[5];
    const float* Wq = (const float*)d_in[6];  const float* bq = (const float*)d_in[7];
    const float* Wk = (const float*)d_in[8];  const float* bk = (const float*)d_in[9];
    const float* Wv = (const float*)d_in[10]; const float* bv = (const float*)d_in[11];
    const float* Wo = (const float*)d_in[12]; const float* bo = (const float*)d_in[13];
    const float* relk  = (const float*)d_in[14];
    const float* relv  = (const float*)d_in[15];
    const float* wpre  = (const float*)d_in[16];
    const float* wpost = (const float*)d_in[17];
    float* out = (float*)d_out;

    float *Q, *Kc, *V, *qbar, *Rbar, *Sc, *Ap, *ctx, *ropeT;
    cudaGetSymbolAddress((void**)&Q,     g_Q);
    cudaGetSymbolAddress((void**)&Kc,    g_K);
    cudaGetSymbolAddress((void**)&V,     g_V);
    cudaGetSymbolAddress((void**)&qbar,  g_qbar);
    cudaGetSymbolAddress((void**)&Rbar,  g_Rbar);
    cudaGetSymbolAddress((void**)&Sc,    g_S);
    cudaGetSymbolAddress((void**)&Ap,    g_Ap);
    cudaGetSymbolAddress((void**)&ctx,   g_ctx);
    cudaGetSymbolAddress((void**)&ropeT, g_ropeT);

    dim3 blk(256);
    const int GS = G_SMEM_BYTES;
    const int TS = T_SMEM_BYTES;

    cudaFuncSetAttribute(rbar_kernel,
                         cudaFuncAttributeMaxDynamicSharedMemorySize, GS);
    cudaFuncSetAttribute(av_fused_kernel,
                         cudaFuncAttributeMaxDynamicSharedMemorySize, GS);
    cudaFuncSetAttribute(wo64_kernel,
                         cudaFuncAttributeMaxDynamicSharedMemorySize, GS);
    cudaFuncSetAttribute(proj64_kernel,
                         cudaFuncAttributeMaxDynamicSharedMemorySize, GS);
    cudaFuncSetAttribute(qk128_kernel,
                         cudaFuncAttributeMaxDynamicSharedMemorySize, TS);
    cudaFuncSetAttribute(mix_softmax_kernel,
                         cudaFuncAttributeMaxDynamicSharedMemorySize, MIX_SMEM);

    rope_table_kernel<<<256, 256>>>(ropeT);

    // Q, K, V projections in ONE launch (G64 tiles, 768 CTAs)
    Proj3 qkv;
    qkv.A[0] = query; qkv.A[1] = key_; qkv.A[2] = value;
    qkv.W[0] = Wq;    qkv.W[1] = Wk;   qkv.W[2] = Wv;
    qkv.C[0] = Q;     qkv.C[1] = Kc;   qkv.C[2] = V;
    qkv.bias[0] = bq; qkv.bias[1] = bk; qkv.bias[2] = bv;
    qkv.pos[0] = qpos; qkv.pos[1] = kpos; qkv.pos[2] = nullptr;
    proj64_kernel<<<dim3(16, 16, 3), blk, GS>>>(qkv, ropeT);

    qbar_kernel<<<512, 256>>>(Q, wpre, qbar);

    // Rbar cols 0..127 = qbar @ relk[128:256]^T (unguarded)
    rbar_kernel<<<dim3(2, 256, 1), blk, GS>>>(qbar, relk + 128 * DD, Rbar);
    // Rbar col 128 = qbar . relk[256] (exact fp32)
    rcol_kernel<<<1024, 256>>>(qbar, relk + 256 * DD, Rbar);

    // QK^T per head, causal tile-skip
    qk128_kernel<<<dim3(8, 8, 32), blk, TS>>>(Q, Kc, Sc);

    // mix + softmax + post-mix + A'
    mix_softmax_kernel<<<dim3(1024, 2), 512, MIX_SMEM>>>(Sc, Rbar, wpre, wpost, Ap);

    // ctx = attn @ v + Ap @ relv' (fused, causal K-limit, rank-1 for j=128)
    av_fused_kernel<<<dim3(1, 8, 32), blk, GS>>>(Sc, V, Ap, relv + 128 * DD, ctx);

    // out = ctx @ Wo^T + bo
    wo64_kernel<<<dim3(16, 16), blk, GS>>>(ctx, Wo, out, bo);
}

// round 15
// speedup vs baseline: 1.0263x; 1.0263x over previous
#include <cuda_runtime.h>
#include <cuda_bf16.h>
#include <math.h>
#include <stdint.h>

// Problem constants
#define BB 2
#define SS 1024
#define HH 16
#define DD 64
#define DM 1024
#define NRS 129        // slim rel width: indices 128..256 of the full table

// Scratch (device globals)
__device__ float g_Q[BB*SS*DM];
__device__ float g_K[BB*SS*DM];
__device__ float g_V[BB*SS*DM];
__device__ float g_qbar[BB*HH*SS*DD];
__device__ float g_Rbar[BB*HH*SS*NRS];
__device__ float g_S[BB*HH*SS*SS];
__device__ float g_Ap[BB*HH*SS*NRS];
__device__ float g_ctx[BB*SS*DM];
__device__ float g_ropeT[2048*64];

__device__ __forceinline__ unsigned f2tf32(float v) {
    unsigned u;
    asm("cvt.rna.tf32.f32 %0, %1;" : "=r"(u) : "f"(v));
    return u;
}

__device__ __forceinline__ void mma_tf32(float c[4],
                                         unsigned a0, unsigned a1, unsigned a2, unsigned a3,
                                         unsigned b0, unsigned b1) {
    asm volatile("mma.sync.aligned.m16n8k8.row.col.f32.tf32.tf32.f32 "
                 "{%0,%1,%2,%3}, {%4,%5,%6,%7}, {%8,%9}, {%0,%1,%2,%3};"
                 : "+f"(c[0]), "+f"(c[1]), "+f"(c[2]), "+f"(c[3])
                 : "r"(a0), "r"(a1), "r"(a2), "r"(a3), "r"(b0), "r"(b1));
}

// ===========================================================================
// 128x128 tf32 GEMM core (warp tile 64x32, K-step 16, double buffered).
// ===========================================================================
#define T_AW 2048
#define T_BW 2048
#define T_BUF (T_AW + T_BW)
#define T_LDST 132
#define T_SMEM_BYTES (64 * T_LDST * 4)

#define GEMM128_BODY(TRANSB_, KTOT, Aptr, Bptr, lda_, ldb_)                          \
    float acc[4][4][4];                                                              \
    _Pragma("unroll")                                                                \
    for (int i = 0; i < 4; i++)                                                      \
        _Pragma("unroll")                                                            \
        for (int j = 0; j < 4; j++)                                                  \
            _Pragma("unroll")                                                        \
            for (int e = 0; e < 4; e++) acc[i][j][e] = 0.f;                          \
    float aPf[8], bPf[8];                                                            \
    int ra = tid >> 4, ka = tid & 15;                                                \
    auto fetchA = [&](int kt) {                                                      \
        _Pragma("unroll")                                                            \
        for (int u = 0; u < 8; u++)                                                  \
            aPf[u] = Aptr[(long)(m0 + ra + u * 16) * lda_ + kt + ka];                \
    };                                                                               \
    auto fetchB = [&](int kt) {                                                      \
        _Pragma("unroll")                                                            \
        for (int u = 0; u < 8; u++) {                                                \
            int idx = tid + u * 256;                                                 \
            if (TRANSB_) {                                                           \
                int n = idx >> 4, kk = idx & 15;                                     \
                bPf[u] = Bptr[(long)(n0 + n) * ldb_ + kt + kk];                      \
            } else {                                                                 \
                int kk = idx >> 7, n = idx & 127;                                    \
                bPf[u] = Bptr[(long)(kt + kk) * ldb_ + n0 + n];                      \
            }                                                                        \
        }                                                                            \
    };                                                                               \
    auto storeBuf = [&](int buf) {                                                   \
        unsigned* Af = base + buf * T_BUF;                                           \
        unsigned* Bf = Af + T_AW;                                                    \
        _Pragma("unroll")                                                            \
        for (int u = 0; u < 8; u++) {                                                \
            int r = ra + u * 16, kk = ka;                                            \
            int blk = r >> 4, rr = r & 15;                                           \
            int ks8 = kk >> 3, kt7 = kk & 7;                                         \
            int dl = ((rr & 7) << 2) | (kt7 & 3);                                    \
            int w  = ((rr >> 3) & 1) | ((kt7 >> 2) << 1);                            \
            Af[(((blk << 1) | ks8) << 7) + (dl << 2) + w] = f2tf32(aPf[u]);          \
        }                                                                            \
        _Pragma("unroll")                                                            \
        for (int u = 0; u < 8; u++) {                                                \
            int idx = tid + u * 256;                                                 \
            int n, kk;                                                               \
            if (TRANSB_) { n = idx >> 4; kk = idx & 15; }                            \
            else         { kk = idx >> 7; n = idx & 127; }                           \
            int nb8 = n >> 3, gg = n & 7;                                            \
            int ks8 = kk >> 3, kt7 = kk & 7;                                         \
            int dl = (gg << 2) | (kt7 & 3);                                          \
            int w  = (kt7 >> 2) & 1;                                                 \
            Bf[(((nb8 << 1) | ks8) << 6) + (dl << 1) + w] = f2tf32(bPf[u]);          \
        }                                                                            \
    };                                                                               \
    fetchA(0); fetchB(0);                                                            \
    storeBuf(0);                                                                     \
    __syncthreads();                                                                 \
    int cur = 0;                                                                     \
    for (int kt = 0; kt < (KTOT); kt += 16) {                                        \
        bool hn = (kt + 16) < (KTOT);                                                \
        if (hn) { fetchA(kt + 16); fetchB(kt + 16); }                                \
        unsigned* Af = base + cur * T_BUF;                                           \
        unsigned* Bf = Af + T_AW;                                                    \
        _Pragma("unroll")                                                            \
        for (int ks8 = 0; ks8 < 2; ks8++) {                                          \
            uint4 av[4];                                                             \
            _Pragma("unroll")                                                        \
            for (int i = 0; i < 4; i++) {                                            \
                int blk = wm * 4 + i;                                                \
                av[i] = *(const uint4*)&Af[(((blk << 1) | ks8) << 7) + (lane << 2)]; \
            }                                                                        \
            _Pragma("unroll")                                                        \
            for (int j = 0; j < 4; j++) {                                            \
                int nb8 = wn * 4 + j;                                                \
                uint2 bv = *(const uint2*)&Bf[(((nb8 << 1) | ks8) << 6) + (lane << 1)]; \
                _Pragma("unroll")                                                    \
                for (int i = 0; i < 4; i++)                                          \
                    mma_tf32(acc[i][j], av[i].x, av[i].y, av[i].z, av[i].w, bv.x, bv.y); \
            }                                                                        \
        }                                                                            \
        if (hn) storeBuf(cur ^ 1);                                                   \
        __syncthreads();                                                             \
        cur ^= 1;                                                                    \
    }

#define STAGE_STORE(step_)                                                           \
    if (wm == (step_)) {                                                             \
        _Pragma("unroll")                                                            \
        for (int i = 0; i < 4; i++)                                                  \
            _Pragma("unroll")                                                        \
            for (int j = 0; j < 4; j++) {                                            \
                int r0 = i * 16 + g;                                                 \
                int c0 = wn * 32 + j * 8 + 2 * t;                                    \
                stage[ r0      * T_LDST + c0    ] = acc[i][j][0];                    \
                stage[ r0      * T_LDST + c0 + 1] = acc[i][j][1];                    \
                stage[(r0 + 8) * T_LDST + c0    ] = acc[i][j][2];                    \
                stage[(r0 + 8) * T_LDST + c0 + 1] = acc[i][j][3];                    \
            }                                                                        \
    }

// ---------------------------------------------------------------------------
// QKV projection kernel (128x128 tile, z selects triple), bias + RoPE fused
// ---------------------------------------------------------------------------
struct Proj3 {
    const float* A[3];
    const float* W[3];
    float*       C[3];
    const float* bias[3];
    const int*   pos[3];
};

__global__ void __launch_bounds__(256, 2)
proj128_kernel(Proj3 p, const float* __restrict__ ropeTab)
{
    extern __shared__ __align__(16) unsigned char dynsm[];
    unsigned* base = (unsigned*)dynsm;
    float* stage = (float*)dynsm;

    int z = blockIdx.z;
    const float* A = p.A[z];
    const float* W = p.W[z];
    float* C = p.C[z];
    const float* bias = p.bias[z];
    const int* posIds = p.pos[z];

    int tid = threadIdx.x;
    int wid = tid >> 5, lane = tid & 31;
    int wm = wid >> 2, wn = wid & 3;
    int g = lane >> 2, t = lane & 3;
    int m0 = blockIdx.y * 128, n0 = blockIdx.x * 128;

    GEMM128_BODY(true, DM, A, W, DM, DM)

    #pragma unroll
    for (int step = 0; step < 2; step++) {
        STAGE_STORE(step)
        __syncthreads();
        #pragma unroll
        for (int u = 0; u < 8; u++) {
            int idx = tid + u * 256;
            int r = idx >> 5, c4 = idx & 31;
            int c = c4 * 4;
            int gm = m0 + step * 64 + r;
            float4 v = *(const float4*)(stage + r * T_LDST + c);
            float4 bv = *(const float4*)(bias + n0 + c);
            v.x += bv.x; v.y += bv.y; v.z += bv.z; v.w += bv.w;
            if (posIds) {
                float4 w = *(const float4*)(stage + r * T_LDST + (c ^ 32));
                float4 bw = *(const float4*)(bias + n0 + (c ^ 32));
                w.x += bw.x; w.y += bw.y; w.z += bw.z; w.w += bw.w;
                int b = gm >> 10, s = gm & 1023;
                int pos = posIds[(b << 10) + s];
                int i0 = c & 31;
                float4 co = *(const float4*)(ropeTab + pos * 64 + i0);
                float4 si = *(const float4*)(ropeTab + pos * 64 + 32 + i0);
                if ((c & 32) == 0) {
                    v.x = v.x * co.x - w.x * si.x;
                    v.y = v.y * co.y - w.y * si.y;
                    v.z = v.z * co.z - w.z * si.z;
                    v.w = v.w * co.w - w.w * si.w;
                } else {
                    v.x = v.x * co.x + w.x * si.x;
                    v.y = v.y * co.y + w.y * si.y;
                    v.z = v.z * co.z + w.z * si.z;
                    v.w = v.w * co.w + w.w * si.w;
                }
            }
            *(float4*)(C + (long)gm * DM + n0 + c) = v;
        }
        __syncthreads();
    }
}

// ---------------------------------------------------------------------------
// QK^T kernel, causal tile skip
// ---------------------------------------------------------------------------
__global__ void __launch_bounds__(256, 2)
qk128_kernel(const float* __restrict__ Qm, const float* __restrict__ Km,
             float* __restrict__ S)
{
    extern __shared__ __align__(16) unsigned char dynsm[];
    unsigned* base = (unsigned*)dynsm;
    float* stage = (float*)dynsm;

    int m0 = blockIdx.y * 128, n0 = blockIdx.x * 128;
    if (n0 > m0) return;

    int z = blockIdx.z;
    int b = z >> 4, h = z & 15;
    const float* A = Qm + (long)b * SS * DM + h * 64;
    const float* Bp = Km + (long)b * SS * DM + h * 64;
    float* C = S + (long)z * SS * SS;

    int tid = threadIdx.x;
    int wid = tid >> 5, lane = tid & 31;
    int wm = wid >> 2, wn = wid & 3;
    int g = lane >> 2, t = lane & 3;

    GEMM128_BODY(true, 64, A, Bp, DM, DM)

    #pragma unroll
    for (int step = 0; step < 2; step++) {
        STAGE_STORE(step)
        __syncthreads();
        #pragma unroll
        for (int u = 0; u < 8; u++) {
            int idx = tid + u * 256;
            int r = idx >> 5, c4 = idx & 31;
            int c = c4 * 4;
            int gm = m0 + step * 64 + r;
            float4 v = *(const float4*)(stage + r * T_LDST + c);
            *(float4*)(C + (long)gm * SS + n0 + c) = v;
        }
        __syncthreads();
    }
}

// ---------------------------------------------------------------------------
// TN=64 machinery
// ---------------------------------------------------------------------------
#define G_AWORDS 4096
#define G_BWORDS 2048
#define G_BUF (G_AWORDS + G_BWORDS)
#define G_LDST 68
#define G_SMEM_BYTES (2 * G_BUF * 4)

#define G64_DECLS                                                                   \
    int tid = threadIdx.x;                                                          \
    int wid = tid >> 5, lane = tid & 31;                                            \
    int wm = wid >> 1;                                                              \
    int wn = wid & 1;                                                               \
    int g = lane >> 2, t = lane & 3;                                                \
    int ra = tid >> 5, ka = tid & 31;                                               \
    float acc[2][4][4];                                                             \
    _Pragma("unroll")                                                               \
    for (int i = 0; i < 2; i++)                                                     \
        _Pragma("unroll")                                                           \
        for (int j = 0; j < 4; j++)                                                 \
            _Pragma("unroll")                                                       \
            for (int e = 0; e < 4; e++) acc[i][j][e] = 0.f;                         \
    float aPf[16], bPf[8];

#define G64_STOREBUF(buf, TRANSB_)                                                  \
    {                                                                               \
        unsigned* Af = base + (buf) * G_BUF;                                        \
        unsigned* Bf = Af + G_AWORDS;                                               \
        _Pragma("unroll")                                                           \
        for (int u = 0; u < 16; u++) {                                              \
            int r = ra + u * 8, kk = ka;                                            \
            int blk = r >> 4, rr = r & 15;                                          \
            int ks8 = kk >> 3, kt7 = kk & 7;                                        \
            int dl = ((rr & 7) << 2) | (kt7 & 3);                                   \
            int w  = ((rr >> 3) & 1) | ((kt7 >> 2) << 1);                           \
            Af[(((blk << 2) + ks8) << 7) + (dl << 2) + w] = f2tf32(aPf[u]);         \
        }                                                                           \
        _Pragma("unroll")                                                           \
        for (int u = 0; u < 8; u++) {                                               \
            int idx = tid + u * 256;                                                \
            int n, kk;                                                              \
            if (TRANSB_) { n = idx >> 5; kk = idx & 31; }                           \
            else         { kk = idx >> 6; n = idx & 63; }                           \
            int nb8 = n >> 3, gg = n & 7;                                           \
            int ks8 = kk >> 3, kt7 = kk & 7;                                        \
            int dl = (gg << 2) | (kt7 & 3);                                         \
            int w  = (kt7 >> 2) & 1;                                                \
            Bf[(((nb8 << 2) + ks8) << 6) + (dl << 1) + w] = f2tf32(bPf[u]);         \
        }                                                                           \
    }

#define G64_MMA(bufc)                                                               \
    {                                                                               \
        unsigned* Af = base + (bufc) * G_BUF;                                       \
        unsigned* Bf = Af + G_AWORDS;                                               \
        _Pragma("unroll")                                                           \
        for (int ks8 = 0; ks8 < 4; ks8++) {                                         \
            uint4 av[2];                                                            \
            _Pragma("unroll")                                                       \
            for (int i = 0; i < 2; i++) {                                           \
                int blk = wm * 2 + i;                                               \
                av[i] = *(const uint4*)&Af[(((blk << 2) + ks8) << 7) + (lane << 2)];\
            }                                                                       \
            _Pragma("unroll")                                                       \
            for (int j = 0; j < 4; j++) {                                           \
                int nb8 = wn * 4 + j;                                               \
                uint2 bv = *(const uint2*)&Bf[(((nb8 << 2) + ks8) << 6) + (lane << 1)]; \
                _Pragma("unroll")                                                   \
                for (int i = 0; i < 2; i++)                                         \
                    mma_tf32(acc[i][j], av[i].x, av[i].y, av[i].z, av[i].w, bv.x, bv.y); \
            }                                                                       \
        }                                                                           \
    }

#define G64_EPILOGUE_STAGE()                                                        \
    _Pragma("unroll")                                                               \
    for (int step = 0; step < 2; step++) {                                          \
        if ((wm >> 1) == step) {                                                    \
            int rbase = (wm & 1) * 32;                                              \
            _Pragma("unroll")                                                       \
            for (int i = 0; i < 2; i++)                                             \
                _Pragma("unroll")                                                   \
                for (int j = 0; j < 4; j++) {                                       \
                    int r0 = rbase + i * 16 + g;                                    \
                    int c0 = wn * 32 + j * 8 + 2 * t;                               \
                    stage[ r0      * G_LDST + c0    ] = acc[i][j][0];               \
                    stage[ r0      * G_LDST + c0 + 1] = acc[i][j][1];               \
                    stage[(r0 + 8) * G_LDST + c0    ] = acc[i][j][2];               \
                    stage[(r0 + 8) * G_LDST + c0 + 1] = acc[i][j][3];               \
                }                                                                   \
        }                                                                           \
        __syncthreads();                                                            \
        G64_WRITE(step)                                                             \
        __syncthreads();                                                            \
    }

// ---------------------------------------------------------------------------
// Rbar kernel: C[32768, 0..127] = A[32768,64] @ B[128,64]^T (unguarded)
// ---------------------------------------------------------------------------
__global__ void __launch_bounds__(256, 2)
rbar_kernel(const float* __restrict__ A, const float* __restrict__ Bm,
            float* __restrict__ C)
{
    extern __shared__ __align__(16) unsigned char dynsm[];
    unsigned* base = (unsigned*)dynsm;
    float* stage = (float*)dynsm;

    const int K = 64;
    int m0 = blockIdx.y * 128, n0 = blockIdx.x * 64;

    G64_DECLS

    auto fetchA = [&](int kt) {
        #pragma unroll
        for (int u = 0; u < 16; u++) {
            int r = ra + u * 8;
            aPf[u] = A[(long)(m0 + r) * 64 + kt + ka];
        }
    };
    auto fetchB = [&](int kt) {
        #pragma unroll
        for (int u = 0; u < 8; u++) {
            int idx = tid + u * 256;
            int n = idx >> 5, kk = idx & 31;
            bPf[u] = Bm[(long)(n0 + n) * 64 + kt + kk];
        }
    };

    fetchA(0); fetchB(0);
    G64_STOREBUF(0, true)
    __syncthreads();
    int cur = 0;
    for (int kt = 0; kt < K; kt += 32) {
        bool hn = (kt + 32) < K;
        if (hn) { fetchA(kt + 32); fetchB(kt + 32); }
        G64_MMA(cur)
        if (hn) G64_STOREBUF(cur ^ 1, true)
        __syncthreads();
        cur ^= 1;
    }

#define G64_WRITE(step_)                                                            \
        _Pragma("unroll")                                                           \
        for (int u = 0; u < 16; u++) {                                              \
            int idx = tid + u * 256;                                                \
            int r = idx >> 6, c = idx & 63;                                         \
            int gm = m0 + (step_) * 64 + r, gn = n0 + c;                            \
            C[(long)gm * NRS + gn] = stage[r * G_LDST + c];                         \
        }
    G64_EPILOGUE_STAGE()
#undef G64_WRITE
}

// ---------------------------------------------------------------------------
// rcol: Rbar column 128 = qbar . relk[256] (exact fp32 dot per row)
// ---------------------------------------------------------------------------
__global__ void rcol_kernel(const float* __restrict__ qbar,
                            const float* __restrict__ relk256,
                            float* __restrict__ Rbar)
{
    __shared__ float rk[64];
    int tid = threadIdx.x;
    if (tid < 64) rk[tid] = relk256[tid];
    __syncthreads();

    int row = blockIdx.x * 32 + (tid >> 3);
    int part = tid & 7;
    const float* qr = qbar + (long)row * 64 + part * 8;
    float4 a0 = *(const float4*)qr;
    float4 a1 = *(const float4*)(qr + 4);
    const float* rp = rk + part * 8;
    float s = a0.x * rp[0] + a0.y * rp[1] + a0.z * rp[2] + a0.w * rp[3]
            + a1.x * rp[4] + a1.y * rp[5] + a1.z * rp[6] + a1.w * rp[7];
    s += __shfl_down_sync(0xffffffffu, s, 4);
    s += __shfl_down_sync(0xffffffffu, s, 2);
    s += __shfl_down_sync(0xffffffffu, s, 1);
    if (part == 0) Rbar[(long)row * NRS + 128] = s;
}

// ---------------------------------------------------------------------------
// Fused AV kernel: ctx = attn @ V + Ap[:,0:128] @ relv'[0:128] + rank-1(j=128)
// ---------------------------------------------------------------------------
__global__ void __launch_bounds__(256, 2)
av_fused_kernel(const float* __restrict__ Sc, const float* __restrict__ Vm,
                const float* __restrict__ Ap, const float* __restrict__ relv2,
                float* __restrict__ ctx)
{
    extern __shared__ __align__(16) unsigned char dynsm[];
    unsigned* base = (unsigned*)dynsm;
    float* stage = (float*)dynsm;

    int m0 = blockIdx.y * 128;
    int z = blockIdx.z;
    int b = z >> 4, h = z & 15;
    int Keff = m0 + 128;

    const float* A  = Sc + (long)z * SS * SS;
    const float* Bv = Vm + (long)b * SS * DM + h * 64;
    const float* A2 = Ap + (long)z * SS * NRS;
    float* C = ctx + (long)b * SS * DM + h * 64;

    G64_DECLS

    auto fetchA1 = [&](int kt) {
        #pragma unroll
        for (int u = 0; u < 16; u++)
            aPf[u] = A[(long)(m0 + ra + u * 8) * SS + kt + ka];
    };
    auto fetchB1 = [&](int kt) {
        #pragma unroll
        for (int u = 0; u < 8; u++) {
            int idx = tid + u * 256;
            int kk = idx >> 6, n = idx & 63;
            bPf[u] = Bv[(long)(kt + kk) * DM + n];
        }
    };
    auto fetchA2 = [&](int kt) {
        #pragma unroll
        for (int u = 0; u < 16; u++)
            aPf[u] = A2[(long)(m0 + ra + u * 8) * NRS + kt + ka];
    };
    auto fetchB2 = [&](int kt) {
        #pragma unroll
        for (int u = 0; u < 8; u++) {
            int idx = tid + u * 256;
            int kk = idx >> 6, n = idx & 63;
            bPf[u] = relv2[(long)(kt + kk) * 64 + n];
        }
    };

    const int K2 = 128;
    fetchA1(0); fetchB1(0);
    G64_STOREBUF(0, false)
    __syncthreads();
    int cur = 0;
    for (int kt = 0; kt < Keff; kt += 32) {
        bool hn = (kt + 32) < Keff;
        if (hn)      { fetchA1(kt + 32); fetchB1(kt + 32); }
        else         { fetchA2(0);       fetchB2(0);       }
        G64_MMA(cur)
        G64_STOREBUF(cur ^ 1, false)
        __syncthreads();
        cur ^= 1;
    }
    for (int kt = 0; kt < K2; kt += 32) {
        bool hn = (kt + 32) < K2;
        if (hn) { fetchA2(kt + 32); fetchB2(kt + 32); }
        G64_MMA(cur)
        if (hn) G64_STOREBUF(cur ^ 1, false)
        __syncthreads();
        cur ^= 1;
    }

#define G64_WRITE(step_)                                                            \
        _Pragma("unroll")                                                           \
        for (int u = 0; u < 4; u++) {                                               \
            int idx = tid + u * 256;                                                \
            int r = idx >> 4, c4 = idx & 15;                                        \
            int c = c4 * 4;                                                         \
            int gm = m0 + (step_) * 64 + r;                                         \
            float4 v = *(const float4*)(stage + r * G_LDST + c);                    \
            float apv = A2[(long)gm * NRS + 128];                                   \
            float4 rv = *(const float4*)(relv2 + 128 * 64 + c);                     \
            v.x += apv * rv.x; v.y += apv * rv.y;                                   \
            v.z += apv * rv.z; v.w += apv * rv.w;                                   \
            *(float4*)(C + (long)gm * DM + c) = v;                                  \
        }
    G64_EPILOGUE_STAGE()
#undef G64_WRITE
}

// ---------------------------------------------------------------------------
// Wo kernel (TN=64 tiles)
// ---------------------------------------------------------------------------
__global__ void __launch_bounds__(256, 2)
wo64_kernel(const float* __restrict__ A, const float* __restrict__ W,
            float* __restrict__ C, const float* __restrict__ bias)
{
    extern __shared__ __align__(16) unsigned char dynsm[];
    unsigned* base = (unsigned*)dynsm;
    float* stage = (float*)dynsm;

    int m0 = blockIdx.y * 128, n0 = blockIdx.x * 64;

    G64_DECLS

    auto fetchA = [&](int kt) {
        #pragma unroll
        for (int u = 0; u < 16; u++)
            aPf[u] = A[(long)(m0 + ra + u * 8) * DM + kt + ka];
    };
    auto fetchB = [&](int kt) {
        #pragma unroll
        for (int u = 0; u < 8; u++) {
            int idx = tid + u * 256;
            int n = idx >> 5, kk = idx & 31;
            bPf[u] = W[(long)(n0 + n) * DM + kt + kk];
        }
    };

    fetchA(0); fetchB(0);
    G64_STOREBUF(0, true)
    __syncthreads();
    int cur = 0;
    for (int kt = 0; kt < DM; kt += 32) {
        bool hn = (kt + 32) < DM;
        if (hn) { fetchA(kt + 32); fetchB(kt + 32); }
        G64_MMA(cur)
        if (hn) G64_STOREBUF(cur ^ 1, true)
        __syncthreads();
        cur ^= 1;
    }

#define G64_WRITE(step_)                                                            \
        _Pragma("unroll")                                                           \
        for (int u = 0; u < 4; u++) {                                               \
            int idx = tid + u * 256;                                                \
            int r = idx >> 4, c4 = idx & 15;                                        \
            int c = c4 * 4;                                                         \
            int gm = m0 + (step_) * 64 + r;                                         \
            float4 v = *(const float4*)(stage + r * G_LDST + c);                    \
            float4 bv = *(const float4*)(bias + n0 + c);                            \
            v.x += bv.x; v.y += bv.y; v.z += bv.z; v.w += bv.w;                     \
            *(float4*)(C + (long)gm * DM + n0 + c) = v;                             \
        }
    G64_EPILOGUE_STAGE()
#undef G64_WRITE
}

// ---------------------------------------------------------------------------
// RoPE table
// ---------------------------------------------------------------------------
__global__ void rope_table_kernel(float* __restrict__ T)
{
    int idx = blockIdx.x * blockDim.x + threadIdx.x;
    if (idx >= 2048 * 32) return;
    int i = idx & 31, pos = idx >> 5;
    double inv = exp(-(double)i / 32.0 * log(10000.0));
    double ds, dc;
    sincos((double)pos * inv, &ds, &dc);
    T[pos * 64 + i]      = (float)dc;
    T[pos * 64 + 32 + i] = (float)ds;
}

// ---------------------------------------------------------------------------
// qbar v2
// ---------------------------------------------------------------------------
__global__ void qbar_kernel(const float* __restrict__ Q, const float* __restrict__ wpre,
                            float* __restrict__ qbar)
{
    __shared__ float sw[256];
    if (threadIdx.x < 256) sw[threadIdx.x] = wpre[threadIdx.x];
    __syncthreads();

    int idx = blockIdx.x * blockDim.x + threadIdx.x;
    if (idx >= BB * SS * DD) return;
    int d = idx & 63;
    int s = (idx >> 6) & 1023;
    int b = idx >> 16;
    const float* qrow = Q + ((size_t)(b * SS + s)) * DM + d;
    float qv[16];
    #pragma unroll
    for (int n = 0; n < 16; n++) qv[n] = qrow[n * 64];
    #pragma unroll
    for (int m = 0; m < 16; m++) {
        float acc = 0.f;
        #pragma unroll
        for (int n = 0; n < 16; n++) acc += sw[n * 16 + m] * qv[n];
        qbar[(((size_t)(b * 16 + m)) * SS + s) * DD + d] = acc;
    }
}

// ---------------------------------------------------------------------------
// mix_softmax — fixed 1024 stride, causal I/O
// ---------------------------------------------------------------------------
#define MIX_SMEM ((16*1024 + 16*NRS + 256 + 256 + 16 + 16) * 4)

__global__ void __launch_bounds__(512)
mix_softmax_kernel(float* __restrict__ S, const float* __restrict__ Rbar,
                   const float* __restrict__ wpre, const float* __restrict__ wpost,
                   float* __restrict__ Ap)
{
    extern __shared__ float shm[];
    float* sm     = shm;
    float* srb    = sm + 16 * 1024;
    float* swpre  = srb + 16 * NRS;
    float* swpost = swpre + 256;
    float* sinv   = swpost + 256;
    float* stail  = sinv + 16;

    int q = blockIdx.x, b = blockIdx.y;
    int tid = threadIdx.x;
    int wid = tid >> 5, lane = tid & 31;
    int KW4 = ((q >> 7) + 1) << 5;
    int KW  = KW4 << 2;

    if (tid < 256) { swpre[tid] = wpre[tid]; swpost[tid] = wpost[tid]; }
    {
        const long rowBase = ((long)(b * 16) * SS + q) * SS;
        for (int tt = tid; tt < 16 * 256; tt += 512) {
            int n = tt >> 8, k4 = tt & 255;
            if (k4 < KW4)
                ((float4*)sm)[n * 256 + k4] =
                    *(const float4*)(S + rowBase + (long)n * SS * SS + k4 * 4);
        }
    }
    for (int tt = tid; tt < 16 * NRS; tt += 512) {
        int m = tt / NRS, j = tt - m * NRS;
        srb[tt] = Rbar[((size_t)(b * 16 + m) * SS + q) * NRS + j];
    }
    __syncthreads();

    for (int k = tid; k <= q; k += 512) {
        float r[16];
        #pragma unroll
        for (int n = 0; n < 16; n++) r[n] = sm[n * 1024 + k];
        int d = q - k;
        int cl = d > 128 ? 128 : d;
        #pragma unroll
        for (int m = 0; m < 16; m++) {
            float accv = 0.f;
            #pragma unroll
            for (int n = 0; n < 16; n++) accv += swpre[n * 16 + m] * r[n];
            sm[m * 1024 + k] = (accv + srb[m * NRS + cl]) * 0.125f;
        }
    }
    __syncthreads();

    {
        int m = wid;
        float mx = -1e30f;
        for (int k = lane; k <= q; k += 32) mx = fmaxf(mx, sm[m * 1024 + k]);
        #pragma unroll
        for (int o = 16; o; o >>= 1) mx = fmaxf(mx, __shfl_xor_sync(0xffffffffu, mx, o));
        float sum = 0.f;
        for (int k = lane; k <= q; k += 32) {
            float p = __expf(sm[m * 1024 + k] - mx);
            sm[m * 1024 + k] = p;
            sum += p;
        }
        #pragma unroll
        for (int o = 16; o; o >>= 1) sum += __shfl_xor_sync(0xffffffffu, sum, o);
        for (int k = q + 1 + lane; k < KW; k += 32) sm[m * 1024 + k] = 0.f;
        if (lane == 0) sinv[m] = 1.f / sum;
    }
    __syncthreads();

    float inv[16];
    #pragma unroll
    for (int m = 0; m < 16; m++) inv[m] = sinv[m];
    for (int k = tid; k <= q; k += 512) {
        float p[16];
        #pragma unroll
        for (int m = 0; m < 16; m++) p[m] = sm[m * 1024 + k] * inv[m];
        #pragma unroll
        for (int n = 0; n < 16; n++) {
            float accv = 0.f;
            #pragma unroll
            for (int m = 0; m < 16; m++) accv += p[m] * swpost[m * 16 + n];
            sm[n * 1024 + k] = accv;
        }
    }
    __syncthreads();

    {
        const long rowBase = ((long)(b * 16) * SS + q) * SS;
        for (int tt = tid; tt < 16 * 256; tt += 512) {
            int n = tt >> 8, k4 = tt & 255;
            if (k4 < KW4)
                *(float4*)(S + rowBase + (long)n * SS * SS + k4 * 4) =
                    ((float4*)sm)[n * 256 + k4];
        }
    }
    {
        int m = wid;
        float ts = 0.f;
        for (int k = lane; k <= q - 128; k += 32) ts += sm[m * 1024 + k];
        #pragma unroll
        for (int o = 16; o; o >>= 1) ts += __shfl_xor_sync(0xffffffffu, ts, o);
        if (lane == 0) stail[m] = ts;
    }
    __syncthreads();

    for (int tt = tid; tt < 16 * NRS; tt += 512) {
        int n = tt / NRS, j = tt - n * NRS;
        float v = 0.f;
        if (j == 128) v = stail[n];
        else {
            int k = q - j;
            if (k >= 0) v = sm[n * 1024 + k];
        }
        Ap[((size_t)(b * 16 + n) * SS + q) * NRS + j] = v;
    }
}

// ---------------------------------------------------------------------------
// Launch sequence
// ---------------------------------------------------------------------------
extern "C" void kernel_launch(void* const* d_in, const int* in_sizes, int n_in,
                              void* d_out, int out_size)
{
    const float* query = (const float*)d_in[0];
    const float* key_  = (const float*)d_in[1];
    const float* value = (const float*)d_in[2];
    const int*   qpos  = (const int*)d_in[4];
    const int*   kpos  = (const int*)d_in[5];
    const float* Wq = (const float*)d_in[6];  const float* bq = (const float*)d_in[7];
    const float* Wk = (const float*)d_in[8];  const float* bk = (const float*)d_in[9];
    const float* Wv = (const float*)d_in[10]; const float* bv = (const float*)d_in[11];
    const float* Wo = (const float*)d_in[12]; const float* bo = (const float*)d_in[13];
    const float* relk  = (const float*)d_in[14];
    const float* relv  = (const float*)d_in[15];
    const float* wpre  = (const float*)d_in[16];
    const float* wpost = (const float*)d_in[17];
    float* out = (float*)d_out;

    float *Q, *Kc, *V, *qbar, *Rbar, *Sc, *Ap, *ctx, *ropeT;
    cudaGetSymbolAddress((void**)&Q,     g_Q);
    cudaGetSymbolAddress((void**)&Kc,    g_K);
    cudaGetSymbolAddress((void**)&V,     g_V);
    cudaGetSymbolAddress((void**)&qbar,  g_qbar);
    cudaGetSymbolAddress((void**)&Rbar,  g_Rbar);
    cudaGetSymbolAddress((void**)&Sc,    g_S);
    cudaGetSymbolAddress((void**)&Ap,    g_Ap);
    cudaGetSymbolAddress((void**)&ctx,   g_ctx);
    cudaGetSymbolAddress((void**)&ropeT, g_ropeT);

    dim3 blk(256);
    const int GS = G_SMEM_BYTES;
    const int TS = T_SMEM_BYTES;

    cudaFuncSetAttribute(rbar_kernel,
                         cudaFuncAttributeMaxDynamicSharedMemorySize, GS);
    cudaFuncSetAttribute(av_fused_kernel,
                         cudaFuncAttributeMaxDynamicSharedMemorySize, GS);
    cudaFuncSetAttribute(wo64_kernel,
                         cudaFuncAttributeMaxDynamicSharedMemorySize, GS);
    cudaFuncSetAttribute(proj128_kernel,
                         cudaFuncAttributeMaxDynamicSharedMemorySize, TS);
    cudaFuncSetAttribute(qk128_kernel,
                         cudaFuncAttributeMaxDynamicSharedMemorySize, TS);
    cudaFuncSetAttribute(mix_softmax_kernel,
                         cudaFuncAttributeMaxDynamicSharedMemorySize, MIX_SMEM);

    rope_table_kernel<<<256, 256>>>(ropeT);

    // Q, K, V projections in ONE launch (128x128 tile, fused bias + RoPE)
    Proj3 qkv;
    qkv.A[0] = query; qkv.A[1] = key_; qkv.A[2] = value;
    qkv.W[0] = Wq;    qkv.W[1] = Wk;   qkv.W[2] = Wv;
    qkv.C[0] = Q;     qkv.C[1] = Kc;   qkv.C[2] = V;
    qkv.bias[0] = bq; qkv.bias[1] = bk; qkv.bias[2] = bv;
    qkv.pos[0] = qpos; qkv.pos[1] = kpos; qkv.pos[2] = nullptr;
    proj128_kernel<<<dim3(8, 16, 3), blk, TS>>>(qkv, ropeT);

    qbar_kernel<<<512, 256>>>(Q, wpre, qbar);

    // Rbar cols 0..127 = qbar @ relk[128:256]^T (unguarded)
    rbar_kernel<<<dim3(2, 256, 1), blk, GS>>>(qbar, relk + 128 * DD, Rbar);
    // Rbar col 128 = qbar . relk[256] (exact fp32)
    rcol_kernel<<<1024, 256>>>(qbar, relk + 256 * DD, Rbar);

    // QK^T per head, causal tile-skip
    qk128_kernel<<<dim3(8, 8, 32), blk, TS>>>(Q, Kc, Sc);

    // mix + softmax + post-mix + A'
    mix_softmax_kernel<<<dim3(1024, 2), 512, MIX_SMEM>>>(Sc, Rbar, wpre, wpost, Ap);

    // ctx = attn @ v + Ap @ relv' (fused, causal K-limit, rank-1 for j=128)
    av_fused_kernel<<<dim3(1, 8, 32), blk, GS>>>(Sc, V, Ap, relv + 128 * DD, ctx);

    // out = ctx @ Wo^T + bo
    wo64_kernel<<<dim3(16, 16), blk, GS>>>(ctx, Wo, out, bo);
}

// round 16
// speedup vs baseline: 1.0376x; 1.0110x over previous
#include <cuda_runtime.h>
#include <cuda_bf16.h>
#include <math.h>
#include <stdint.h>

// Problem constants
#define BB 2
#define SS 1024
#define HH 16
#define DD 64
#define DM 1024
#define NRS 129        // slim rel width: indices 128..256 of the full table

// Scratch (device globals)
__device__ float g_Q[BB*SS*DM];
__device__ float g_K[BB*SS*DM];
__device__ float g_V[BB*SS*DM];
__device__ float g_qbar[BB*HH*SS*DD];
__device__ float g_Rbar[BB*HH*SS*NRS];
__device__ float g_S[BB*HH*SS*SS];
__device__ float g_Ap[BB*HH*SS*NRS];
__device__ float g_ctx[BB*SS*DM];
__device__ float g_ropeT[2048*64];

__device__ __forceinline__ unsigned f2tf32(float v) {
    unsigned u;
    asm("cvt.rna.tf32.f32 %0, %1;" : "=r"(u) : "f"(v));
    return u;
}

__device__ __forceinline__ void mma_tf32(float c[4],
                                         unsigned a0, unsigned a1, unsigned a2, unsigned a3,
                                         unsigned b0, unsigned b1) {
    asm volatile("mma.sync.aligned.m16n8k8.row.col.f32.tf32.tf32.f32 "
                 "{%0,%1,%2,%3}, {%4,%5,%6,%7}, {%8,%9}, {%0,%1,%2,%3};"
                 : "+f"(c[0]), "+f"(c[1]), "+f"(c[2]), "+f"(c[3])
                 : "r"(a0), "r"(a1), "r"(a2), "r"(a3), "r"(b0), "r"(b1));
}

// ===========================================================================
// 128x128 tf32 GEMM core (warp tile 64x32, K-step 16, double buffered).
// ===========================================================================
#define T_AW 2048
#define T_BW 2048
#define T_BUF (T_AW + T_BW)
#define T_LDST 132
#define T_SMEM_BYTES (64 * T_LDST * 4)

#define GEMM128_BODY(TRANSB_, KTOT, Aptr, Bptr, lda_, ldb_)                          \
    float acc[4][4][4];                                                              \
    _Pragma("unroll")                                                                \
    for (int i = 0; i < 4; i++)                                                      \
        _Pragma("unroll")                                                            \
        for (int j = 0; j < 4; j++)                                                  \
            _Pragma("unroll")                                                        \
            for (int e = 0; e < 4; e++) acc[i][j][e] = 0.f;                          \
    float aPf[8], bPf[8];                                                            \
    int ra = tid >> 4, ka = tid & 15;                                                \
    auto fetchA = [&](int kt) {                                                      \
        _Pragma("unroll")                                                            \
        for (int u = 0; u < 8; u++)                                                  \
            aPf[u] = Aptr[(long)(m0 + ra + u * 16) * lda_ + kt + ka];                \
    };                                                                               \
    auto fetchB = [&](int kt) {                                                      \
        _Pragma("unroll")                                                            \
        for (int u = 0; u < 8; u++) {                                                \
            int idx = tid + u * 256;                                                 \
            if (TRANSB_) {                                                           \
                int n = idx >> 4, kk = idx & 15;                                     \
                bPf[u] = Bptr[(long)(n0 + n) * ldb_ + kt + kk];                      \
            } else {                                                                 \
                int kk = idx >> 7, n = idx & 127;                                    \
                bPf[u] = Bptr[(long)(kt + kk) * ldb_ + n0 + n];                      \
            }                                                                        \
        }                                                                            \
    };                                                                               \
    auto storeBuf = [&](int buf) {                                                   \
        unsigned* Af = base + buf * T_BUF;                                           \
        unsigned* Bf = Af + T_AW;                                                    \
        _Pragma("unroll")                                                            \
        for (int u = 0; u < 8; u++) {                                                \
            int r = ra + u * 16, kk = ka;                                            \
            int blk = r >> 4, rr = r & 15;                                           \
            int ks8 = kk >> 3, kt7 = kk & 7;                                         \
            int dl = ((rr & 7) << 2) | (kt7 & 3);                                    \
            int w  = ((rr >> 3) & 1) | ((kt7 >> 2) << 1);                            \
            Af[(((blk << 1) | ks8) << 7) + (dl << 2) + w] = f2tf32(aPf[u]);          \
        }                                                                            \
        _Pragma("unroll")                                                            \
        for (int u = 0; u < 8; u++) {                                                \
            int idx = tid + u * 256;                                                 \
            int n, kk;                                                               \
            if (TRANSB_) { n = idx >> 4; kk = idx & 15; }                            \
            else         { kk = idx >> 7; n = idx & 127; }                           \
            int nb8 = n >> 3, gg = n & 7;                                            \
            int ks8 = kk >> 3, kt7 = kk & 7;                                         \
            int dl = (gg << 2) | (kt7 & 3);                                          \
            int w  = (kt7 >> 2) & 1;                                                 \
            Bf[(((nb8 << 1) | ks8) << 6) + (dl << 1) + w] = f2tf32(bPf[u]);          \
        }                                                                            \
    };                                                                               \
    fetchA(0); fetchB(0);                                                            \
    storeBuf(0);                                                                     \
    __syncthreads();                                                                 \
    int cur = 0;                                                                     \
    for (int kt = 0; kt < (KTOT); kt += 16) {                                        \
        bool hn = (kt + 16) < (KTOT);                                                \
        if (hn) { fetchA(kt + 16); fetchB(kt + 16); }                                \
        unsigned* Af = base + cur * T_BUF;                                           \
        unsigned* Bf = Af + T_AW;                                                    \
        _Pragma("unroll")                                                            \
        for (int ks8 = 0; ks8 < 2; ks8++) {                                          \
            uint4 av[4];                                                             \
            _Pragma("unroll")                                                        \
            for (int i = 0; i < 4; i++) {                                            \
                int blk = wm * 4 + i;                                                \
                av[i] = *(const uint4*)&Af[(((blk << 1) | ks8) << 7) + (lane << 2)]; \
            }                                                                        \
            _Pragma("unroll")                                                        \
            for (int j = 0; j < 4; j++) {                                            \
                int nb8 = wn * 4 + j;                                                \
                uint2 bv = *(const uint2*)&Bf[(((nb8 << 1) | ks8) << 6) + (lane << 1)]; \
                _Pragma("unroll")                                                    \
                for (int i = 0; i < 4; i++)                                          \
                    mma_tf32(acc[i][j], av[i].x, av[i].y, av[i].z, av[i].w, bv.x, bv.y); \
            }                                                                        \
        }                                                                            \
        if (hn) storeBuf(cur ^ 1);                                                   \
        __syncthreads();                                                             \
        cur ^= 1;                                                                    \
    }

#define STAGE_STORE(step_)                                                           \
    if (wm == (step_)) {                                                             \
        _Pragma("unroll")                                                            \
        for (int i = 0; i < 4; i++)                                                  \
            _Pragma("unroll")                                                        \
            for (int j = 0; j < 4; j++) {                                            \
                int r0 = i * 16 + g;                                                 \
                int c0 = wn * 32 + j * 8 + 2 * t;                                    \
                stage[ r0      * T_LDST + c0    ] = acc[i][j][0];                    \
                stage[ r0      * T_LDST + c0 + 1] = acc[i][j][1];                    \
                stage[(r0 + 8) * T_LDST + c0    ] = acc[i][j][2];                    \
                stage[(r0 + 8) * T_LDST + c0 + 1] = acc[i][j][3];                    \
            }                                                                        \
    }

// ---------------------------------------------------------------------------
// QKV projection kernel (128x128 tile, z selects triple), bias + RoPE fused
// ---------------------------------------------------------------------------
struct Proj3 {
    const float* A[3];
    const float* W[3];
    float*       C[3];
    const float* bias[3];
    const int*   pos[3];
};

__global__ void __launch_bounds__(256, 2)
proj128_kernel(Proj3 p, const float* __restrict__ ropeTab)
{
    extern __shared__ __align__(16) unsigned char dynsm[];
    unsigned* base = (unsigned*)dynsm;
    float* stage = (float*)dynsm;

    int z = blockIdx.z;
    const float* A = p.A[z];
    const float* W = p.W[z];
    float* C = p.C[z];
    const float* bias = p.bias[z];
    const int* posIds = p.pos[z];

    int tid = threadIdx.x;
    int wid = tid >> 5, lane = tid & 31;
    int wm = wid >> 2, wn = wid & 3;
    int g = lane >> 2, t = lane & 3;
    int m0 = blockIdx.y * 128, n0 = blockIdx.x * 128;

    GEMM128_BODY(true, DM, A, W, DM, DM)

    #pragma unroll
    for (int step = 0; step < 2; step++) {
        STAGE_STORE(step)
        __syncthreads();
        #pragma unroll
        for (int u = 0; u < 8; u++) {
            int idx = tid + u * 256;
            int r = idx >> 5, c4 = idx & 31;
            int c = c4 * 4;
            int gm = m0 + step * 64 + r;
            float4 v = *(const float4*)(stage + r * T_LDST + c);
            float4 bv = *(const float4*)(bias + n0 + c);
            v.x += bv.x; v.y += bv.y; v.z += bv.z; v.w += bv.w;
            if (posIds) {
                float4 w = *(const float4*)(stage + r * T_LDST + (c ^ 32));
                float4 bw = *(const float4*)(bias + n0 + (c ^ 32));
                w.x += bw.x; w.y += bw.y; w.z += bw.z; w.w += bw.w;
                int b = gm >> 10, s = gm & 1023;
                int pos = posIds[(b << 10) + s];
                int i0 = c & 31;
                float4 co = *(const float4*)(ropeTab + pos * 64 + i0);
                float4 si = *(const float4*)(ropeTab + pos * 64 + 32 + i0);
                if ((c & 32) == 0) {
                    v.x = v.x * co.x - w.x * si.x;
                    v.y = v.y * co.y - w.y * si.y;
                    v.z = v.z * co.z - w.z * si.z;
                    v.w = v.w * co.w - w.w * si.w;
                } else {
                    v.x = v.x * co.x + w.x * si.x;
                    v.y = v.y * co.y + w.y * si.y;
                    v.z = v.z * co.z + w.z * si.z;
                    v.w = v.w * co.w + w.w * si.w;
                }
            }
            *(float4*)(C + (long)gm * DM + n0 + c) = v;
        }
        __syncthreads();
    }
}

// ---------------------------------------------------------------------------
// QK^T kernel, causal tile skip
// ---------------------------------------------------------------------------
__global__ void __launch_bounds__(256, 2)
qk128_kernel(const float* __restrict__ Qm, const float* __restrict__ Km,
             float* __restrict__ S)
{
    extern __shared__ __align__(16) unsigned char dynsm[];
    unsigned* base = (unsigned*)dynsm;
    float* stage = (float*)dynsm;

    int m0 = blockIdx.y * 128, n0 = blockIdx.x * 128;
    if (n0 > m0) return;

    int z = blockIdx.z;
    int b = z >> 4, h = z & 15;
    const float* A = Qm + (long)b * SS * DM + h * 64;
    const float* Bp = Km + (long)b * SS * DM + h * 64;
    float* C = S + (long)z * SS * SS;

    int tid = threadIdx.x;
    int wid = tid >> 5, lane = tid & 31;
    int wm = wid >> 2, wn = wid & 3;
    int g = lane >> 2, t = lane & 3;

    GEMM128_BODY(true, 64, A, Bp, DM, DM)

    #pragma unroll
    for (int step = 0; step < 2; step++) {
        STAGE_STORE(step)
        __syncthreads();
        #pragma unroll
        for (int u = 0; u < 8; u++) {
            int idx = tid + u * 256;
            int r = idx >> 5, c4 = idx & 31;
            int c = c4 * 4;
            int gm = m0 + step * 64 + r;
            float4 v = *(const float4*)(stage + r * T_LDST + c);
            *(float4*)(C + (long)gm * SS + n0 + c) = v;
        }
        __syncthreads();
    }
}

// ---------------------------------------------------------------------------
// TN=64 machinery
// ---------------------------------------------------------------------------
#define G_AWORDS 4096
#define G_BWORDS 2048
#define G_BUF (G_AWORDS + G_BWORDS)
#define G_LDST 68
#define G_SMEM_BYTES (2 * G_BUF * 4)

#define G64_DECLS                                                                   \
    int tid = threadIdx.x;                                                          \
    int wid = tid >> 5, lane = tid & 31;                                            \
    int wm = wid >> 1;                                                              \
    int wn = wid & 1;                                                               \
    int g = lane >> 2, t = lane & 3;                                                \
    int ra = tid >> 5, ka = tid & 31;                                               \
    float acc[2][4][4];                                                             \
    _Pragma("unroll")                                                               \
    for (int i = 0; i < 2; i++)                                                     \
        _Pragma("unroll")                                                           \
        for (int j = 0; j < 4; j++)                                                 \
            _Pragma("unroll")                                                       \
            for (int e = 0; e < 4; e++) acc[i][j][e] = 0.f;                         \
    float aPf[16], bPf[8];

#define G64_STOREBUF(buf, TRANSB_)                                                  \
    {                                                                               \
        unsigned* Af = base + (buf) * G_BUF;                                        \
        unsigned* Bf = Af + G_AWORDS;                                               \
        _Pragma("unroll")                                                           \
        for (int u = 0; u < 16; u++) {                                              \
            int r = ra + u * 8, kk = ka;                                            \
            int blk = r >> 4, rr = r & 15;                                          \
            int ks8 = kk >> 3, kt7 = kk & 7;                                        \
            int dl = ((rr & 7) << 2) | (kt7 & 3);                                   \
            int w  = ((rr >> 3) & 1) | ((kt7 >> 2) << 1);                           \
            Af[(((blk << 2) + ks8) << 7) + (dl << 2) + w] = f2tf32(aPf[u]);         \
        }                                                                           \
        _Pragma("unroll")                                                           \
        for (int u = 0; u < 8; u++) {                                               \
            int idx = tid + u * 256;                                                \
            int n, kk;                                                              \
            if (TRANSB_) { n = idx >> 5; kk = idx & 31; }                           \
            else         { kk = idx >> 6; n = idx & 63; }                           \
            int nb8 = n >> 3, gg = n & 7;                                           \
            int ks8 = kk >> 3, kt7 = kk & 7;                                        \
            int dl = (gg << 2) | (kt7 & 3);                                         \
            int w  = (kt7 >> 2) & 1;                                                \
            Bf[(((nb8 << 2) + ks8) << 6) + (dl << 1) + w] = f2tf32(bPf[u]);         \
        }                                                                           \
    }

#define G64_MMA(bufc)                                                               \
    {                                                                               \
        unsigned* Af = base + (bufc) * G_BUF;                                       \
        unsigned* Bf = Af + G_AWORDS;                                               \
        _Pragma("unroll")                                                           \
        for (int ks8 = 0; ks8 < 4; ks8++) {                                         \
            uint4 av[2];                                                            \
            _Pragma("unroll")                                                       \
            for (int i = 0; i < 2; i++) {                                           \
                int blk = wm * 2 + i;                                               \
                av[i] = *(const uint4*)&Af[(((blk << 2) + ks8) << 7) + (lane << 2)];\
            }                                                                       \
            _Pragma("unroll")                                                       \
            for (int j = 0; j < 4; j++) {                                           \
                int nb8 = wn * 4 + j;                                               \
                uint2 bv = *(const uint2*)&Bf[(((nb8 << 2) + ks8) << 6) + (lane << 1)]; \
                _Pragma("unroll")                                                   \
                for (int i = 0; i < 2; i++)                                         \
                    mma_tf32(acc[i][j], av[i].x, av[i].y, av[i].z, av[i].w, bv.x, bv.y); \
            }                                                                       \
        }                                                                           \
    }

#define G64_EPILOGUE_STAGE()                                                        \
    _Pragma("unroll")                                                               \
    for (int step = 0; step < 2; step++) {                                          \
        if ((wm >> 1) == step) {                                                    \
            int rbase = (wm & 1) * 32;                                              \
            _Pragma("unroll")                                                       \
            for (int i = 0; i < 2; i++)                                             \
                _Pragma("unroll")                                                   \
                for (int j = 0; j < 4; j++) {                                       \
                    int r0 = rbase + i * 16 + g;                                    \
                    int c0 = wn * 32 + j * 8 + 2 * t;                               \
                    stage[ r0      * G_LDST + c0    ] = acc[i][j][0];               \
                    stage[ r0      * G_LDST + c0 + 1] = acc[i][j][1];               \
                    stage[(r0 + 8) * G_LDST + c0    ] = acc[i][j][2];               \
                    stage[(r0 + 8) * G_LDST + c0 + 1] = acc[i][j][3];               \
                }                                                                   \
        }                                                                           \
        __syncthreads();                                                            \
        G64_WRITE(step)                                                             \
        __syncthreads();                                                            \
    }

// ---------------------------------------------------------------------------
// Rbar kernel: C[32768, 0..127] = A[32768,64] @ B[128,64]^T (unguarded)
// ---------------------------------------------------------------------------
__global__ void __launch_bounds__(256, 2)
rbar_kernel(const float* __restrict__ A, const float* __restrict__ Bm,
            float* __restrict__ C)
{
    extern __shared__ __align__(16) unsigned char dynsm[];
    unsigned* base = (unsigned*)dynsm;
    float* stage = (float*)dynsm;

    const int K = 64;
    int m0 = blockIdx.y * 128, n0 = blockIdx.x * 64;

    G64_DECLS

    auto fetchA = [&](int kt) {
        #pragma unroll
        for (int u = 0; u < 16; u++) {
            int r = ra + u * 8;
            aPf[u] = A[(long)(m0 + r) * 64 + kt + ka];
        }
    };
    auto fetchB = [&](int kt) {
        #pragma unroll
        for (int u = 0; u < 8; u++) {
            int idx = tid + u * 256;
            int n = idx >> 5, kk = idx & 31;
            bPf[u] = Bm[(long)(n0 + n) * 64 + kt + kk];
        }
    };

    fetchA(0); fetchB(0);
    G64_STOREBUF(0, true)
    __syncthreads();
    int cur = 0;
    for (int kt = 0; kt < K; kt += 32) {
        bool hn = (kt + 32) < K;
        if (hn) { fetchA(kt + 32); fetchB(kt + 32); }
        G64_MMA(cur)
        if (hn) G64_STOREBUF(cur ^ 1, true)
        __syncthreads();
        cur ^= 1;
    }

#define G64_WRITE(step_)                                                            \
        _Pragma("unroll")                                                           \
        for (int u = 0; u < 16; u++) {                                              \
            int idx = tid + u * 256;                                                \
            int r = idx >> 6, c = idx & 63;                                         \
            int gm = m0 + (step_) * 64 + r, gn = n0 + c;                            \
            C[(long)gm * NRS + gn] = stage[r * G_LDST + c];                         \
        }
    G64_EPILOGUE_STAGE()
#undef G64_WRITE
}

// ---------------------------------------------------------------------------
// rcol: Rbar column 128 = qbar . relk[256] (exact fp32 dot per row)
// ---------------------------------------------------------------------------
__global__ void rcol_kernel(const float* __restrict__ qbar,
                            const float* __restrict__ relk256,
                            float* __restrict__ Rbar)
{
    __shared__ float rk[64];
    int tid = threadIdx.x;
    if (tid < 64) rk[tid] = relk256[tid];
    __syncthreads();

    int row = blockIdx.x * 32 + (tid >> 3);
    int part = tid & 7;
    const float* qr = qbar + (long)row * 64 + part * 8;
    float4 a0 = *(const float4*)qr;
    float4 a1 = *(const float4*)(qr + 4);
    const float* rp = rk + part * 8;
    float s = a0.x * rp[0] + a0.y * rp[1] + a0.z * rp[2] + a0.w * rp[3]
            + a1.x * rp[4] + a1.y * rp[5] + a1.z * rp[6] + a1.w * rp[7];
    s += __shfl_down_sync(0xffffffffu, s, 4);
    s += __shfl_down_sync(0xffffffffu, s, 2);
    s += __shfl_down_sync(0xffffffffu, s, 1);
    if (part == 0) Rbar[(long)row * NRS + 128] = s;
}

// ---------------------------------------------------------------------------
// Fused AV kernel: ctx = attn @ V + Ap[:,0:128] @ relv'[0:128] + rank-1(j=128)
// LPT order: largest m0 (most K-work) scheduled first.
// ---------------------------------------------------------------------------
__global__ void __launch_bounds__(256, 2)
av_fused_kernel(const float* __restrict__ Sc, const float* __restrict__ Vm,
                const float* __restrict__ Ap, const float* __restrict__ relv2,
                float* __restrict__ ctx)
{
    extern __shared__ __align__(16) unsigned char dynsm[];
    unsigned* base = (unsigned*)dynsm;
    float* stage = (float*)dynsm;

    int m0 = (7 - (int)blockIdx.y) * 128;     // LPT: longest first
    int z = blockIdx.z;
    int b = z >> 4, h = z & 15;
    int Keff = m0 + 128;

    const float* A  = Sc + (long)z * SS * SS;
    const float* Bv = Vm + (long)b * SS * DM + h * 64;
    const float* A2 = Ap + (long)z * SS * NRS;
    float* C = ctx + (long)b * SS * DM + h * 64;

    G64_DECLS

    auto fetchA1 = [&](int kt) {
        #pragma unroll
        for (int u = 0; u < 16; u++)
            aPf[u] = A[(long)(m0 + ra + u * 8) * SS + kt + ka];
    };
    auto fetchB1 = [&](int kt) {
        #pragma unroll
        for (int u = 0; u < 8; u++) {
            int idx = tid + u * 256;
            int kk = idx >> 6, n = idx & 63;
            bPf[u] = Bv[(long)(kt + kk) * DM + n];
        }
    };
    auto fetchA2 = [&](int kt) {
        #pragma unroll
        for (int u = 0; u < 16; u++)
            aPf[u] = A2[(long)(m0 + ra + u * 8) * NRS + kt + ka];
    };
    auto fetchB2 = [&](int kt) {
        #pragma unroll
        for (int u = 0; u < 8; u++) {
            int idx = tid + u * 256;
            int kk = idx >> 6, n = idx & 63;
            bPf[u] = relv2[(long)(kt + kk) * 64 + n];
        }
    };

    const int K2 = 128;
    fetchA1(0); fetchB1(0);
    G64_STOREBUF(0, false)
    __syncthreads();
    int cur = 0;
    for (int kt = 0; kt < Keff; kt += 32) {
        bool hn = (kt + 32) < Keff;
        if (hn)      { fetchA1(kt + 32); fetchB1(kt + 32); }
        else         { fetchA2(0);       fetchB2(0);       }
        G64_MMA(cur)
        G64_STOREBUF(cur ^ 1, false)
        __syncthreads();
        cur ^= 1;
    }
    for (int kt = 0; kt < K2; kt += 32) {
        bool hn = (kt + 32) < K2;
        if (hn) { fetchA2(kt + 32); fetchB2(kt + 32); }
        G64_MMA(cur)
        if (hn) G64_STOREBUF(cur ^ 1, false)
        __syncthreads();
        cur ^= 1;
    }

#define G64_WRITE(step_)                                                            \
        _Pragma("unroll")                                                           \
        for (int u = 0; u < 4; u++) {                                               \
            int idx = tid + u * 256;                                                \
            int r = idx >> 4, c4 = idx & 15;                                        \
            int c = c4 * 4;                                                         \
            int gm = m0 + (step_) * 64 + r;                                         \
            float4 v = *(const float4*)(stage + r * G_LDST + c);                    \
            float apv = A2[(long)gm * NRS + 128];                                   \
            float4 rv = *(const float4*)(relv2 + 128 * 64 + c);                     \
            v.x += apv * rv.x; v.y += apv * rv.y;                                   \
            v.z += apv * rv.z; v.w += apv * rv.w;                                   \
            *(float4*)(C + (long)gm * DM + c) = v;                                  \
        }
    G64_EPILOGUE_STAGE()
#undef G64_WRITE
}

// ---------------------------------------------------------------------------
// Wo kernel (TN=64 tiles)
// ---------------------------------------------------------------------------
__global__ void __launch_bounds__(256, 2)
wo64_kernel(const float* __restrict__ A, const float* __restrict__ W,
            float* __restrict__ C, const float* __restrict__ bias)
{
    extern __shared__ __align__(16) unsigned char dynsm[];
    unsigned* base = (unsigned*)dynsm;
    float* stage = (float*)dynsm;

    int m0 = blockIdx.y * 128, n0 = blockIdx.x * 64;

    G64_DECLS

    auto fetchA = [&](int kt) {
        #pragma unroll
        for (int u = 0; u < 16; u++)
            aPf[u] = A[(long)(m0 + ra + u * 8) * DM + kt + ka];
    };
    auto fetchB = [&](int kt) {
        #pragma unroll
        for (int u = 0; u < 8; u++) {
            int idx = tid + u * 256;
            int n = idx >> 5, kk = idx & 31;
            bPf[u] = W[(long)(n0 + n) * DM + kt + kk];
        }
    };

    fetchA(0); fetchB(0);
    G64_STOREBUF(0, true)
    __syncthreads();
    int cur = 0;
    for (int kt = 0; kt < DM; kt += 32) {
        bool hn = (kt + 32) < DM;
        if (hn) { fetchA(kt + 32); fetchB(kt + 32); }
        G64_MMA(cur)
        if (hn) G64_STOREBUF(cur ^ 1, true)
        __syncthreads();
        cur ^= 1;
    }

#define G64_WRITE(step_)                                                            \
        _Pragma("unroll")                                                           \
        for (int u = 0; u < 4; u++) {                                               \
            int idx = tid + u * 256;                                                \
            int r = idx >> 4, c4 = idx & 15;                                        \
            int c = c4 * 4;                                                         \
            int gm = m0 + (step_) * 64 + r;                                         \
            float4 v = *(const float4*)(stage + r * G_LDST + c);                    \
            float4 bv = *(const float4*)(bias + n0 + c);                            \
            v.x += bv.x; v.y += bv.y; v.z += bv.z; v.w += bv.w;                     \
            *(float4*)(C + (long)gm * DM + n0 + c) = v;                             \
        }
    G64_EPILOGUE_STAGE()
#undef G64_WRITE
}

// ---------------------------------------------------------------------------
// RoPE table
// ---------------------------------------------------------------------------
__global__ void rope_table_kernel(float* __restrict__ T)
{
    int idx = blockIdx.x * blockDim.x + threadIdx.x;
    if (idx >= 2048 * 32) return;
    int i = idx & 31, pos = idx >> 5;
    double inv = exp(-(double)i / 32.0 * log(10000.0));
    double ds, dc;
    sincos((double)pos * inv, &ds, &dc);
    T[pos * 64 + i]      = (float)dc;
    T[pos * 64 + 32 + i] = (float)ds;
}

// ---------------------------------------------------------------------------
// qbar v2
// ---------------------------------------------------------------------------
__global__ void qbar_kernel(const float* __restrict__ Q, const float* __restrict__ wpre,
                            float* __restrict__ qbar)
{
    __shared__ float sw[256];
    if (threadIdx.x < 256) sw[threadIdx.x] = wpre[threadIdx.x];
    __syncthreads();

    int idx = blockIdx.x * blockDim.x + threadIdx.x;
    if (idx >= BB * SS * DD) return;
    int d = idx & 63;
    int s = (idx >> 6) & 1023;
    int b = idx >> 16;
    const float* qrow = Q + ((size_t)(b * SS + s)) * DM + d;
    float qv[16];
    #pragma unroll
    for (int n = 0; n < 16; n++) qv[n] = qrow[n * 64];
    #pragma unroll
    for (int m = 0; m < 16; m++) {
        float acc = 0.f;
        #pragma unroll
        for (int n = 0; n < 16; n++) acc += sw[n * 16 + m] * qv[n];
        qbar[(((size_t)(b * 16 + m)) * SS + s) * DD + d] = acc;
    }
}

// ---------------------------------------------------------------------------
// mix_softmax — fixed 1024 stride, causal I/O.
// LPT order: q = 1023 - blockIdx.x (longest rows first).
// ---------------------------------------------------------------------------
#define MIX_SMEM ((16*1024 + 16*NRS + 256 + 256 + 16 + 16) * 4)

__global__ void __launch_bounds__(512)
mix_softmax_kernel(float* __restrict__ S, const float* __restrict__ Rbar,
                   const float* __restrict__ wpre, const float* __restrict__ wpost,
                   float* __restrict__ Ap)
{
    extern __shared__ float shm[];
    float* sm     = shm;
    float* srb    = sm + 16 * 1024;
    float* swpre  = srb + 16 * NRS;
    float* swpost = swpre + 256;
    float* sinv   = swpost + 256;
    float* stail  = sinv + 16;

    int q = 1023 - (int)blockIdx.x;      // LPT: longest rows first
    int b = blockIdx.y;
    int tid = threadIdx.x;
    int wid = tid >> 5, lane = tid & 31;
    int KW4 = ((q >> 7) + 1) << 5;
    int KW  = KW4 << 2;

    if (tid < 256) { swpre[tid] = wpre[tid]; swpost[tid] = wpost[tid]; }
    {
        const long rowBase = ((long)(b * 16) * SS + q) * SS;
        for (int tt = tid; tt < 16 * 256; tt += 512) {
            int n = tt >> 8, k4 = tt & 255;
            if (k4 < KW4)
                ((float4*)sm)[n * 256 + k4] =
                    *(const float4*)(S + rowBase + (long)n * SS * SS + k4 * 4);
        }
    }
    for (int tt = tid; tt < 16 * NRS; tt += 512) {
        int m = tt / NRS, j = tt - m * NRS;
        srb[tt] = Rbar[((size_t)(b * 16 + m) * SS + q) * NRS + j];
    }
    __syncthreads();

    for (int k = tid; k <= q; k += 512) {
        float r[16];
        #pragma unroll
        for (int n = 0; n < 16; n++) r[n] = sm[n * 1024 + k];
        int d = q - k;
        int cl = d > 128 ? 128 : d;
        #pragma unroll
        for (int m = 0; m < 16; m++) {
            float accv = 0.f;
            #pragma unroll
            for (int n = 0; n < 16; n++) accv += swpre[n * 16 + m] * r[n];
            sm[m * 1024 + k] = (accv + srb[m * NRS + cl]) * 0.125f;
        }
    }
    __syncthreads();

    {
        int m = wid;
        float mx = -1e30f;
        for (int k = lane; k <= q; k += 32) mx = fmaxf(mx, sm[m * 1024 + k]);
        #pragma unroll
        for (int o = 16; o; o >>= 1) mx = fmaxf(mx, __shfl_xor_sync(0xffffffffu, mx, o));
        float sum = 0.f;
        for (int k = lane; k <= q; k += 32) {
            float p = __expf(sm[m * 1024 + k] - mx);
            sm[m * 1024 + k] = p;
            sum += p;
        }
        #pragma unroll
        for (int o = 16; o; o >>= 1) sum += __shfl_xor_sync(0xffffffffu, sum, o);
        for (int k = q + 1 + lane; k < KW; k += 32) sm[m * 1024 + k] = 0.f;
        if (lane == 0) sinv[m] = 1.f / sum;
    }
    __syncthreads();

    float inv[16];
    #pragma unroll
    for (int m = 0; m < 16; m++) inv[m] = sinv[m];
    for (int k = tid; k <= q; k += 512) {
        float p[16];
        #pragma unroll
        for (int m = 0; m < 16; m++) p[m] = sm[m * 1024 + k] * inv[m];
        #pragma unroll
        for (int n = 0; n < 16; n++) {
            float accv = 0.f;
            #pragma unroll
            for (int m = 0; m < 16; m++) accv += p[m] * swpost[m * 16 + n];
            sm[n * 1024 + k] = accv;
        }
    }
    __syncthreads();

    {
        const long rowBase = ((long)(b * 16) * SS + q) * SS;
        for (int tt = tid; tt < 16 * 256; tt += 512) {
            int n = tt >> 8, k4 = tt & 255;
            if (k4 < KW4)
                *(float4*)(S + rowBase + (long)n * SS * SS + k4 * 4) =
                    ((float4*)sm)[n * 256 + k4];
        }
    }
    {
        int m = wid;
        float ts = 0.f;
        for (int k = lane; k <= q - 128; k += 32) ts += sm[m * 1024 + k];
        #pragma unroll
        for (int o = 16; o; o >>= 1) ts += __shfl_xor_sync(0xffffffffu, ts, o);
        if (lane == 0) stail[m] = ts;
    }
    __syncthreads();

    for (int tt = tid; tt < 16 * NRS; tt += 512) {
        int n = tt / NRS, j = tt - n * NRS;
        float v = 0.f;
        if (j == 128) v = stail[n];
        else {
            int k = q - j;
            if (k >= 0) v = sm[n * 1024 + k];
        }
        Ap[((size_t)(b * 16 + n) * SS + q) * NRS + j] = v;
    }
}

// ---------------------------------------------------------------------------
// Launch sequence
// ---------------------------------------------------------------------------
extern "C" void kernel_launch(void* const* d_in, const int* in_sizes, int n_in,
                              void* d_out, int out_size)
{
    const float* query = (const float*)d_in[0];
    const float* key_  = (const float*)d_in[1];
    const float* value = (const float*)d_in[2];
    const int*   qpos  = (const int*)d_in[4];
    const int*   kpos  = (const int*)d_in[5];
    const float* Wq = (const float*)d_in[6];  const float* bq = (const float*)d_in[7];
    const float* Wk = (const float*)d_in[8];  const float* bk = (const float*)d_in[9];
    const float* Wv = (const float*)d_in[10]; const float* bv = (const float*)d_in[11];
    const float* Wo = (const float*)d_in[12]; const float* bo = (const float*)d_in[13];
    const float* relk  = (const float*)d_in[14];
    const float* relv  = (const float*)d_in[15];
    const float* wpre  = (const float*)d_in[16];
    const float* wpost = (const float*)d_in[17];
    float* out = (float*)d_out;

    float *Q, *Kc, *V, *qbar, *Rbar, *Sc, *Ap, *ctx, *ropeT;
    cudaGetSymbolAddress((void**)&Q,     g_Q);
    cudaGetSymbolAddress((void**)&Kc,    g_K);
    cudaGetSymbolAddress((void**)&V,     g_V);
    cudaGetSymbolAddress((void**)&qbar,  g_qbar);
    cudaGetSymbolAddress((void**)&Rbar,  g_Rbar);
    cudaGetSymbolAddress((void**)&Sc,    g_S);
    cudaGetSymbolAddress((void**)&Ap,    g_Ap);
    cudaGetSymbolAddress((void**)&ctx,   g_ctx);
    cudaGetSymbolAddress((void**)&ropeT, g_ropeT);

    dim3 blk(256);
    const int GS = G_SMEM_BYTES;
    const int TS = T_SMEM_BYTES;

    cudaFuncSetAttribute(rbar_kernel,
                         cudaFuncAttributeMaxDynamicSharedMemorySize, GS);
    cudaFuncSetAttribute(av_fused_kernel,
                         cudaFuncAttributeMaxDynamicSharedMemorySize, GS);
    cudaFuncSetAttribute(wo64_kernel,
                         cudaFuncAttributeMaxDynamicSharedMemorySize, GS);
    cudaFuncSetAttribute(proj128_kernel,
                         cudaFuncAttributeMaxDynamicSharedMemorySize, TS);
    cudaFuncSetAttribute(qk128_kernel,
                         cudaFuncAttributeMaxDynamicSharedMemorySize, TS);
    cudaFuncSetAttribute(mix_softmax_kernel,
                         cudaFuncAttributeMaxDynamicSharedMemorySize, MIX_SMEM);

    rope_table_kernel<<<256, 256>>>(ropeT);

    // Q, K, V projections in ONE launch (128x128 tile, fused bias + RoPE)
    Proj3 qkv;
    qkv.A[0] = query; qkv.A[1] = key_; qkv.A[2] = value;
    qkv.W[0] = Wq;    qkv.W[1] = Wk;   qkv.W[2] = Wv;
    qkv.C[0] = Q;     qkv.C[1] = Kc;   qkv.C[2] = V;
    qkv.bias[0] = bq; qkv.bias[1] = bk; qkv.bias[2] = bv;
    qkv.pos[0] = qpos; qkv.pos[1] = kpos; qkv.pos[2] = nullptr;
    proj128_kernel<<<dim3(8, 16, 3), blk, TS>>>(qkv, ropeT);

    qbar_kernel<<<512, 256>>>(Q, wpre, qbar);

    // Rbar cols 0..127 = qbar @ relk[128:256]^T (unguarded)
    rbar_kernel<<<dim3(2, 256, 1), blk, GS>>>(qbar, relk + 128 * DD, Rbar);
    // Rbar col 128 = qbar . relk[256] (exact fp32)
    rcol_kernel<<<1024, 256>>>(qbar, relk + 256 * DD, Rbar);

    // QK^T per head, causal tile-skip
    qk128_kernel<<<dim3(8, 8, 32), blk, TS>>>(Q, Kc, Sc);

    // mix + softmax + post-mix + A' (LPT row order)
    mix_softmax_kernel<<<dim3(1024, 2), 512, MIX_SMEM>>>(Sc, Rbar, wpre, wpost, Ap);

    // ctx = attn @ v + Ap @ relv' (fused, causal K-limit, rank-1, LPT order)
    av_fused_kernel<<<dim3(1, 8, 32), blk, GS>>>(Sc, V, Ap, relv + 128 * DD, ctx);

    // out = ctx @ Wo^T + bo
    wo64_kernel<<<dim3(16, 16), blk, GS>>>(ctx, Wo, out, bo);
}